// round 4
// baseline (speedup 1.0000x reference)
#include <cuda_runtime.h>
#include <cstdint>
#include <cstddef>

#define N_ 20000
#define E_ 640000
#define MB (1048576ull)

// ---------------- scratch layout (MiB offsets) ----------------
static const size_t O_CSR  = 0;               // int[2E] src in csr order (6 MiB)
static const size_t O_CSRD = 6*MB;            // int[2E] dst per csr entry
static const size_t O_CNT  = 12*MB;           // int[2N]
static const size_t O_OFF  = 13*MB;           // int[2N]
static const size_t O_CUR  = 14*MB;           // int[2N]
static const size_t O_EXPV = 15*MB;           // float[2E*8]  40.96 MiB -> 42
static const size_t O_IVZ  = 57*MB;           // float[2N*8]
static const size_t O_H1   = 59*MB;           // float[2*N*128] 19.6 -> 20
static const size_t O_S1S  = 79*MB;           // float[2*N*8]
static const size_t O_S1D  = 81*MB;
static const size_t O_H1C  = 83*MB;           // float[N*128] 9.8 -> 10
static const size_t O_S2S  = 93*MB;
static const size_t O_S2D  = 95*MB;
static const size_t O_WS   = 97*MB;           // float[16*128]
static const size_t O_WD   = 97*MB + 16384;
static const size_t O_W2C  = 98*MB;           // float[2048*64]
static const size_t O_BC   = 98*MB + 524288;  // float[64]
static const size_t O_AGG  = 99*MB;           // float[N*2048] 156.25 MiB -> 99..256
static const size_t O_SRC  = 99*MB;           // int[2E] (temp, dead before agg written)
static const size_t O_DST  = 105*MB;          // int[2E] (temp)
static const size_t O_H2P  = 256*MB;          // float[N*64]
static const size_t SCRATCH_BYTES = 262*MB;

__device__ __align__(256) unsigned char g_scratch[SCRATCH_BYTES];

__device__ __forceinline__ float eluf(float x) { return x > 0.f ? x : expm1f(x); }
__device__ __forceinline__ float lrelu(float x) { return x > 0.f ? x : 0.2f * x; }

// ---------------- cvt with inline dtype detect + dst histogram ----------------
__global__ void k_cvt(const void* pa, const void* pb, int* src, int* dst, int* cnt) {
    int t = blockIdx.y;
    const void* p = t ? pb : pa;
    // per-warp dtype detect: int64 arrays have zero odd 32-bit words
    unsigned ov = ((const unsigned*)p)[1 + 2 * (threadIdx.x & 31)];
    int is64 = __all_sync(0xffffffffu, ov == 0u);
    int i = blockIdx.x * blockDim.x + threadIdx.x;
    if (i >= E_) return;
    int s, d;
    if (is64) {
        const long long* q = (const long long*)p;
        s = (int)q[i]; d = (int)q[E_ + i];
    } else {
        const int* q = (const int*)p;
        s = q[i]; d = q[E_ + i];
    }
    src[t * E_ + i] = s;
    dst[t * E_ + i] = d;
    atomicAdd(&cnt[t * N_ + d], 1);
}

// ---------------- exclusive scan, 4 elems/thread ----------------
__global__ void k_scan(const int* __restrict__ cnt, int* __restrict__ offs, int* __restrict__ cur)
{
    int t = blockIdx.x;
    const int4* c4 = (const int4*)(cnt + t * N_);
    int4* o4 = (int4*)(offs + t * N_);
    int4* q4 = (int4*)(cur + t * N_);
    __shared__ int wsum[32];
    __shared__ int sbase;
    int tid = threadIdx.x, lane = tid & 31, w = tid >> 5;
    if (tid == 0) sbase = 0;
    __syncthreads();
    const int N4 = N_ / 4;   // 5000
    for (int i0 = 0; i0 < N4; i0 += 1024) {
        int i = i0 + tid;
        int4 c = make_int4(0, 0, 0, 0);
        if (i < N4) c = c4[i];
        int s = c.x + c.y + c.z + c.w;
        int x = s;
#pragma unroll
        for (int ofs = 1; ofs < 32; ofs <<= 1) {
            int y = __shfl_up_sync(0xffffffffu, x, ofs);
            if (lane >= ofs) x += y;
        }
        if (lane == 31) wsum[w] = x;
        __syncthreads();
        if (w == 0) {
            int v = wsum[lane];
#pragma unroll
            for (int ofs = 1; ofs < 32; ofs <<= 1) {
                int y = __shfl_up_sync(0xffffffffu, v, ofs);
                if (lane >= ofs) v += y;
            }
            wsum[lane] = v;
        }
        __syncthreads();
        int excl = sbase + (w ? wsum[w - 1] : 0) + x - s;
        if (i < N4) {
            int4 r;
            r.x = excl;
            r.y = excl + c.x;
            r.z = r.y + c.y;
            r.w = r.z + c.z;
            o4[i] = r; q4[i] = r;
        }
        __syncthreads();
        if (tid == 0) sbase += wsum[31];
        __syncthreads();
    }
}

__global__ void k_scatter(const int* __restrict__ src, const int* __restrict__ dst,
                          int* __restrict__ cur, int* __restrict__ csr, int* __restrict__ csrd)
{
    int i = blockIdx.x * blockDim.x + threadIdx.x;
    if (i >= 2 * E_) return;
    int t = (i >= E_) ? 1 : 0;
    int e = i - t * E_;
    int s = src[t * E_ + e], d = dst[t * E_ + e];
    int pos = atomicAdd(&cur[t * N_ + d], 1);
    csr[(size_t)t * E_ + pos] = s;
    csrd[(size_t)t * E_ + pos] = d;
}

// precompute: W2cat (scaled 1/16), score-projection vectors, combined bias
__global__ void k_prep(const float* __restrict__ W2, const float* __restrict__ a2s,
                       const float* __restrict__ a2d, const float* __restrict__ b2,
                       float* __restrict__ W2cat, float* __restrict__ ws,
                       float* __restrict__ wd, float* __restrict__ bc)
{
    int i = blockIdx.x * blockDim.x + threadIdx.x;
    if (i < 131072) {
        int o = i & 63, k = i >> 6;
        int t = k >> 10, r = k & 1023, h = r >> 7, c = r & 127;
        W2cat[i] = W2[t * 65536 + c * 512 + h * 64 + o] * 0.0625f;
    } else if (i < 133120) {
        int j = i - 131072;
        int t = j >> 10, r = j & 1023, h = r >> 7, c = r & 127;
        const float* wrow = W2 + t * 65536 + c * 512 + h * 64;
        const float* av = a2s + t * 512 + h * 64;
        float acc = 0.f;
        for (int o = 0; o < 64; o++) acc += wrow[o] * av[o];
        ws[j] = acc;
    } else if (i < 135168) {
        int j = i - 133120;
        int t = j >> 10, r = j & 1023, h = r >> 7, c = r & 127;
        const float* wrow = W2 + t * 65536 + c * 512 + h * 64;
        const float* av = a2d + t * 512 + h * 64;
        float acc = 0.f;
        for (int o = 0; o < 64; o++) acc += wrow[o] * av[o];
        wd[j] = acc;
    } else if (i < 135232) {
        int o = i - 135168;
        bc[o] = 0.5f * (b2[o] + b2[64 + o]);
    }
}

// ---------------- SGEMM (layer-1) ----------------
template<int K>
__global__ void __launch_bounds__(256) k_sgemm(
    const float* __restrict__ A, const float* __restrict__ B,
    float* __restrict__ C, int n, int M)
{
    __shared__ float As[16][128];
    __shared__ float Bs[16][128];
    const int tid = threadIdx.x;
    const int rquad = (tid >> 4) << 2;
    const int cquad = (tid & 15) << 2;
    const int rowBase = blockIdx.x * 128;
    const int colBase = blockIdx.y * 128;
    const int b = blockIdx.z;
    const float* Bb = B + (size_t)b * K * M + colBase;
    float* Cb = C + (size_t)b * (size_t)n * M + colBase;

    float acc[8][8];
#pragma unroll
    for (int i = 0; i < 8; i++)
#pragma unroll
        for (int j = 0; j < 8; j++) acc[i][j] = 0.f;

    for (int k0 = 0; k0 < K; k0 += 16) {
#pragma unroll
        for (int i = 0; i < 2; i++) {
            int idx = tid + (i << 8);
            int r = idx >> 2;
            int c = (idx & 3) << 2;
            float4 v = make_float4(0.f, 0.f, 0.f, 0.f);
            int gr = rowBase + r;
            if (gr < n) v = *(const float4*)(A + (size_t)gr * K + k0 + c);
            As[c + 0][r] = v.x; As[c + 1][r] = v.y;
            As[c + 2][r] = v.z; As[c + 3][r] = v.w;
        }
#pragma unroll
        for (int i = 0; i < 2; i++) {
            int idx = tid + (i << 8);
            int r = idx >> 5;
            int c = (idx & 31) << 2;
            float4 v = *(const float4*)(Bb + (size_t)(k0 + r) * M + c);
            *(float4*)&Bs[r][c] = v;
        }
        __syncthreads();
#pragma unroll
        for (int kk = 0; kk < 16; kk++) {
            float a[8], bb[8];
            *(float4*)&a[0]  = *(const float4*)&As[kk][rquad];
            *(float4*)&a[4]  = *(const float4*)&As[kk][rquad + 64];
            *(float4*)&bb[0] = *(const float4*)&Bs[kk][cquad];
            *(float4*)&bb[4] = *(const float4*)&Bs[kk][cquad + 64];
#pragma unroll
            for (int i = 0; i < 8; i++)
#pragma unroll
                for (int j = 0; j < 8; j++)
                    acc[i][j] = fmaf(a[i], bb[j], acc[i][j]);
        }
        __syncthreads();
    }
#pragma unroll
    for (int i = 0; i < 8; i++) {
        int gr = rowBase + rquad + (i < 4 ? i : 64 + i - 4);
        if (gr < n) {
            *(float4*)(Cb + (size_t)gr * M + cquad) =
                make_float4(acc[i][0], acc[i][1], acc[i][2], acc[i][3]);
            *(float4*)(Cb + (size_t)gr * M + cquad + 64) =
                make_float4(acc[i][4], acc[i][5], acc[i][6], acc[i][7]);
        }
    }
}

// ---------------- layer-1 attention scores: warp per node ----------------
template<int C>
__global__ void k_scores(const float* __restrict__ h,
                         const float* __restrict__ a_src,
                         const float* __restrict__ a_dst,
                         float* __restrict__ ss, float* __restrict__ sd)
{
    const int ROW = 8 * C;
    int wid = (blockIdx.x * blockDim.x + threadIdx.x) >> 5;
    int lane = threadIdx.x & 31;
    int t = blockIdx.y;
    if (wid >= N_) return;
    const float* hr = h + (size_t)t * N_ * ROW + (size_t)wid * ROW;
    const float* as = a_src + t * ROW;
    const float* ad = a_dst + t * ROW;
    int head = lane >> 2;
    float ps = 0.f, pd = 0.f;
#pragma unroll
    for (int i = 0; i < C / 16; i++) {
        int off = lane * (ROW / 32) + i * 4;
        float4 v = *(const float4*)(hr + off);
        float4 w = *(const float4*)(as + off);
        float4 u = *(const float4*)(ad + off);
        ps += v.x * w.x + v.y * w.y + v.z * w.z + v.w * w.w;
        pd += v.x * u.x + v.y * u.y + v.z * u.z + v.w * u.w;
    }
    ps += __shfl_xor_sync(0xffffffffu, ps, 1);
    ps += __shfl_xor_sync(0xffffffffu, ps, 2);
    pd += __shfl_xor_sync(0xffffffffu, pd, 1);
    pd += __shfl_xor_sync(0xffffffffu, pd, 2);
    if ((lane & 3) == 0) {
        ss[t * N_ * 8 + wid * 8 + head] = ps;
        sd[t * N_ * 8 + wid * 8 + head] = pd;
    }
}

// ---------------- exp(leakyrelu(scores)) per csr entry, edge-parallel ----------------
__global__ void k_expv(const int* __restrict__ csr, const int* __restrict__ csrd,
                       const float* __restrict__ ss, const float* __restrict__ sd,
                       float* __restrict__ expv)
{
    int t = blockIdx.y;
    int i = blockIdx.x * blockDim.x + threadIdx.x;   // entry*8 + h
    int entry = i >> 3, h = i & 7;
    int s = __ldg(&csr[(size_t)t * E_ + entry]);
    int d = __ldg(&csrd[(size_t)t * E_ + entry]);
    float ev = lrelu(__ldg(&ss[(size_t)t * N_ * 8 + s * 8 + h]) +
                     __ldg(&sd[(size_t)t * N_ * 8 + d * 8 + h]));
    expv[((size_t)t * E_ + entry) * 8 + h] = __expf(ev);
}

// ---------------- softmax denominators: warp per dst, coalesced ----------------
__global__ void k_z(const int* __restrict__ offs, const int* __restrict__ cnt,
                    const float* __restrict__ expv, float* __restrict__ ivz)
{
    int t = blockIdx.y;
    int d = blockIdx.x * 8 + (threadIdx.x >> 5);
    int lane = threadIdx.x & 31;
    if (d >= N_) return;
    int beg = offs[t * N_ + d], n = cnt[t * N_ + d];
    const float* ep = expv + ((size_t)t * E_ + beg) * 8;
    float zp = 0.f;
    for (int e = lane >> 3; e < n; e += 4)
        zp += ep[e * 8 + (lane & 7)];
    zp += __shfl_xor_sync(0xffffffffu, zp, 8);
    zp += __shfl_xor_sync(0xffffffffu, zp, 16);
    if (lane < 8)
        ivz[((size_t)t * N_ + d) * 8 + lane] = 1.f / zp;
}

// ---------------- layer-1 GAT aggregate: warp per dst, chunked/unrolled ----------------
__global__ void __launch_bounds__(256) k_gat1(
    const int* __restrict__ offs, const int* __restrict__ cnt, const int* __restrict__ csr,
    const float* __restrict__ expv, const float* __restrict__ ivz,
    const float* __restrict__ h1, const float* __restrict__ b1,
    float* __restrict__ h1c)
{
    __shared__ float sa[8][256];
    int w = threadIdx.x >> 5;
    int d = blockIdx.x * 8 + w;
    int lane = threadIdx.x & 31;
    if (d >= N_) return;
    int hd = lane >> 2;
    float4 acc = make_float4(0.f, 0.f, 0.f, 0.f);
    for (int t = 0; t < 2; t++) {
        int beg = offs[t * N_ + d], n = cnt[t * N_ + d];
        const float4* izp = (const float4*)(ivz + ((size_t)t * N_ + d) * 8);
        float4 iz0 = izp[0], iz1 = izp[1];
        const float* ht = h1 + (size_t)t * N_ * 128;
        for (int c0 = 0; c0 < n; c0 += 32) {
            int m = n - c0; if (m > 32) m = 32;
            int sL = 0;
            if (lane < m) {
                size_t g = (size_t)t * E_ + beg + c0 + lane;
                sL = csr[g];
                float4 e0 = *(const float4*)(expv + g * 8);
                float4 e1 = *(const float4*)(expv + g * 8 + 4);
                e0.x *= iz0.x; e0.y *= iz0.y; e0.z *= iz0.z; e0.w *= iz0.w;
                e1.x *= iz1.x; e1.y *= iz1.y; e1.z *= iz1.z; e1.w *= iz1.w;
                *(float4*)&sa[w][lane * 8] = e0;
                *(float4*)&sa[w][lane * 8 + 4] = e1;
            }
            __syncwarp();
#pragma unroll
            for (int j = 0; j < 32; j++) {
                if (j < m) {
                    int sj = __shfl_sync(0xffffffffu, sL, j);
                    float a = sa[w][j * 8 + hd];
                    float4 v = *(const float4*)(ht + (size_t)sj * 128 + lane * 4);
                    acc.x = fmaf(a, v.x, acc.x);
                    acc.y = fmaf(a, v.y, acc.y);
                    acc.z = fmaf(a, v.z, acc.z);
                    acc.w = fmaf(a, v.w, acc.w);
                }
            }
            __syncwarp();
        }
    }
    float4 bb0 = *(const float4*)(b1 + lane * 4);
    float4 bb1 = *(const float4*)(b1 + 128 + lane * 4);
    float4 r;
    r.x = eluf(0.5f * (acc.x + bb0.x + bb1.x));
    r.y = eluf(0.5f * (acc.y + bb0.y + bb1.y));
    r.z = eluf(0.5f * (acc.z + bb0.z + bb1.z));
    r.w = eluf(0.5f * (acc.w + bb0.w + bb1.w));
    *(float4*)(h1c + (size_t)d * 128 + lane * 4) = r;
}

// ---------------- layer-2 scores from projected vectors ----------------
__global__ void k_scores2(const float* __restrict__ h1c,
                          const float* __restrict__ ws, const float* __restrict__ wd,
                          float* __restrict__ s2s, float* __restrict__ s2d)
{
    int node = blockIdx.x * 8 + (threadIdx.x >> 5);
    int lane = threadIdx.x & 31;
    if (node >= N_) return;
    float4 v = *(const float4*)(h1c + (size_t)node * 128 + lane * 4);
#pragma unroll
    for (int c = 0; c < 16; c++) {
        float4 w = *(const float4*)(ws + c * 128 + lane * 4);
        float p = v.x * w.x + v.y * w.y + v.z * w.z + v.w * w.w;
        p += __shfl_xor_sync(0xffffffffu, p, 16);
        p += __shfl_xor_sync(0xffffffffu, p, 8);
        p += __shfl_xor_sync(0xffffffffu, p, 4);
        p += __shfl_xor_sync(0xffffffffu, p, 2);
        p += __shfl_xor_sync(0xffffffffu, p, 1);
        float4 u = *(const float4*)(wd + c * 128 + lane * 4);
        float q = v.x * u.x + v.y * u.y + v.z * u.z + v.w * u.w;
        q += __shfl_xor_sync(0xffffffffu, q, 16);
        q += __shfl_xor_sync(0xffffffffu, q, 8);
        q += __shfl_xor_sync(0xffffffffu, q, 4);
        q += __shfl_xor_sync(0xffffffffu, q, 2);
        q += __shfl_xor_sync(0xffffffffu, q, 1);
        if (lane == 0) {
            s2s[(c >> 3) * N_ * 8 + node * 8 + (c & 7)] = p;
            s2d[(c >> 3) * N_ * 8 + node * 8 + (c & 7)] = q;
        }
    }
}

// ---------------- layer-2 aggregate (h1c domain): warp per dst ----------------
__global__ void __launch_bounds__(256) k_gat2(
    const int* __restrict__ offs, const int* __restrict__ cnt, const int* __restrict__ csr,
    const float* __restrict__ expv, const float* __restrict__ ivz,
    const float* __restrict__ h1c, float* __restrict__ agg)
{
    __shared__ float sa[8][256];
    int w = threadIdx.x >> 5;
    int d = blockIdx.x * 8 + w;
    int lane = threadIdx.x & 31;
    if (d >= N_) return;
    for (int t = 0; t < 2; t++) {
        int beg = offs[t * N_ + d], n = cnt[t * N_ + d];
        const float4* izp = (const float4*)(ivz + ((size_t)t * N_ + d) * 8);
        float4 iz0 = izp[0], iz1 = izp[1];
        float4 acc[8];
#pragma unroll
        for (int h = 0; h < 8; h++) acc[h] = make_float4(0.f, 0.f, 0.f, 0.f);
        for (int c0 = 0; c0 < n; c0 += 32) {
            int m = n - c0; if (m > 32) m = 32;
            int sL = 0;
            if (lane < m) {
                size_t g = (size_t)t * E_ + beg + c0 + lane;
                sL = csr[g];
                float4 e0 = *(const float4*)(expv + g * 8);
                float4 e1 = *(const float4*)(expv + g * 8 + 4);
                e0.x *= iz0.x; e0.y *= iz0.y; e0.z *= iz0.z; e0.w *= iz0.w;
                e1.x *= iz1.x; e1.y *= iz1.y; e1.z *= iz1.z; e1.w *= iz1.w;
                *(float4*)&sa[w][lane * 8] = e0;
                *(float4*)&sa[w][lane * 8 + 4] = e1;
            }
            __syncwarp();
#pragma unroll
            for (int j = 0; j < 32; j++) {
                if (j < m) {
                    int sj = __shfl_sync(0xffffffffu, sL, j);
                    float4 a0 = *(const float4*)&sa[w][j * 8];
                    float4 a1 = *(const float4*)&sa[w][j * 8 + 4];
                    float4 v = *(const float4*)(h1c + (size_t)sj * 128 + lane * 4);
                    acc[0].x = fmaf(a0.x, v.x, acc[0].x); acc[0].y = fmaf(a0.x, v.y, acc[0].y);
                    acc[0].z = fmaf(a0.x, v.z, acc[0].z); acc[0].w = fmaf(a0.x, v.w, acc[0].w);
                    acc[1].x = fmaf(a0.y, v.x, acc[1].x); acc[1].y = fmaf(a0.y, v.y, acc[1].y);
                    acc[1].z = fmaf(a0.y, v.z, acc[1].z); acc[1].w = fmaf(a0.y, v.w, acc[1].w);
                    acc[2].x = fmaf(a0.z, v.x, acc[2].x); acc[2].y = fmaf(a0.z, v.y, acc[2].y);
                    acc[2].z = fmaf(a0.z, v.z, acc[2].z); acc[2].w = fmaf(a0.z, v.w, acc[2].w);
                    acc[3].x = fmaf(a0.w, v.x, acc[3].x); acc[3].y = fmaf(a0.w, v.y, acc[3].y);
                    acc[3].z = fmaf(a0.w, v.z, acc[3].z); acc[3].w = fmaf(a0.w, v.w, acc[3].w);
                    acc[4].x = fmaf(a1.x, v.x, acc[4].x); acc[4].y = fmaf(a1.x, v.y, acc[4].y);
                    acc[4].z = fmaf(a1.x, v.z, acc[4].z); acc[4].w = fmaf(a1.x, v.w, acc[4].w);
                    acc[5].x = fmaf(a1.y, v.x, acc[5].x); acc[5].y = fmaf(a1.y, v.y, acc[5].y);
                    acc[5].z = fmaf(a1.y, v.z, acc[5].z); acc[5].w = fmaf(a1.y, v.w, acc[5].w);
                    acc[6].x = fmaf(a1.z, v.x, acc[6].x); acc[6].y = fmaf(a1.z, v.y, acc[6].y);
                    acc[6].z = fmaf(a1.z, v.z, acc[6].z); acc[6].w = fmaf(a1.z, v.w, acc[6].w);
                    acc[7].x = fmaf(a1.w, v.x, acc[7].x); acc[7].y = fmaf(a1.w, v.y, acc[7].y);
                    acc[7].z = fmaf(a1.w, v.z, acc[7].z); acc[7].w = fmaf(a1.w, v.w, acc[7].w);
                }
            }
            __syncwarp();
        }
        float* ob = agg + (size_t)d * 2048 + t * 1024;
#pragma unroll
        for (int h = 0; h < 8; h++)
            *(float4*)(ob + h * 128 + lane * 4) = acc[h];
    }
}

// ---------------- deferred layer-2 GEMM: [N x 2048] @ [2048 x 64] ----------------
__global__ void __launch_bounds__(256) k_gemm3(
    const float* __restrict__ A, const float* __restrict__ B, float* __restrict__ C)
{
    __shared__ float As[16][128];
    __shared__ float Bs[16][64];
    int tid = threadIdx.x;
    int rg = (tid >> 4) << 2;
    int cg = (tid & 15) << 2;
    int rowBase = blockIdx.x * 128;
    float acc[8][4];
#pragma unroll
    for (int i = 0; i < 8; i++)
#pragma unroll
        for (int j = 0; j < 4; j++) acc[i][j] = 0.f;

    for (int k0 = 0; k0 < 2048; k0 += 16) {
#pragma unroll
        for (int i = 0; i < 2; i++) {
            int idx = tid + (i << 8);
            int r = idx >> 2;
            int c = (idx & 3) << 2;
            float4 v = make_float4(0.f, 0.f, 0.f, 0.f);
            int gr = rowBase + r;
            if (gr < N_) v = *(const float4*)(A + (size_t)gr * 2048 + k0 + c);
            As[c + 0][r] = v.x; As[c + 1][r] = v.y;
            As[c + 2][r] = v.z; As[c + 3][r] = v.w;
        }
        {
            int r = tid >> 4;
            int c = (tid & 15) << 2;
            float4 v = *(const float4*)(B + (size_t)(k0 + r) * 64 + c);
            *(float4*)&Bs[r][c] = v;
        }
        __syncthreads();
#pragma unroll
        for (int kk = 0; kk < 16; kk++) {
            float a[8], b[4];
            *(float4*)&a[0] = *(const float4*)&As[kk][rg];
            *(float4*)&a[4] = *(const float4*)&As[kk][rg + 64];
            *(float4*)&b[0] = *(const float4*)&Bs[kk][cg];
#pragma unroll
            for (int i = 0; i < 8; i++)
#pragma unroll
                for (int j = 0; j < 4; j++)
                    acc[i][j] = fmaf(a[i], b[j], acc[i][j]);
        }
        __syncthreads();
    }
#pragma unroll
    for (int i = 0; i < 8; i++) {
        int gr = rowBase + rg + (i < 4 ? i : 64 + i - 4);
        if (gr < N_)
            *(float4*)(C + (size_t)gr * 64 + cg) =
                make_float4(acc[i][0], acc[i][1], acc[i][2], acc[i][3]);
    }
}

// ---------------- classifier (bias + ELU fused): warp per node ----------------
__global__ void k_classifier(const float* __restrict__ h, const float* __restrict__ bc,
                             const float* __restrict__ Wc1, const float* __restrict__ bc1,
                             const float* __restrict__ Wc2, const float* __restrict__ bc2,
                             float* __restrict__ out)
{
    int wid = (blockIdx.x * blockDim.x + threadIdx.x) >> 5;
    int lane = threadIdx.x & 31;
    if (wid >= N_) return;
    const float* hr = h + (size_t)wid * 64;
    float acc = bc1[lane];
#pragma unroll
    for (int c = 0; c < 64; c++) {
        float hv = eluf(__ldg(hr + c) + __ldg(bc + c));
        acc = fmaf(hv, Wc1[c * 32 + lane], acc);
    }
    acc = fmaxf(acc, 0.f);
    float p0 = acc * Wc2[lane * 2];
    float p1 = acc * Wc2[lane * 2 + 1];
#pragma unroll
    for (int o = 16; o >= 1; o >>= 1) {
        p0 += __shfl_xor_sync(0xffffffffu, p0, o);
        p1 += __shfl_xor_sync(0xffffffffu, p1, o);
    }
    if (lane == 0) {
        out[wid * 2 + 0] = p0 + bc2[0];
        out[wid * 2 + 1] = p1 + bc2[1];
    }
}

// ---------------- launch ----------------
extern "C" void kernel_launch(void* const* d_in, const int* in_sizes, int n_in,
                              void* d_out, int out_size)
{
    const float* x    = (const float*)d_in[0];
    const void*  eia  = d_in[1];
    const void*  eib  = d_in[2];
    const float* W1   = (const float*)d_in[3];
    const float* a1s  = (const float*)d_in[4];
    const float* a1d  = (const float*)d_in[5];
    const float* b1   = (const float*)d_in[6];
    const float* W2   = (const float*)d_in[7];
    const float* a2s  = (const float*)d_in[8];
    const float* a2d  = (const float*)d_in[9];
    const float* b2   = (const float*)d_in[10];
    const float* Wc1  = (const float*)d_in[11];
    const float* bc1  = (const float*)d_in[12];
    const float* Wc2  = (const float*)d_in[13];
    const float* bc2  = (const float*)d_in[14];
    float* out = (float*)d_out;

    void* basev = nullptr;
    cudaGetSymbolAddress(&basev, g_scratch);
    unsigned char* base = (unsigned char*)basev;

    int*   p_csr  = (int*)(base + O_CSR);
    int*   p_csrd = (int*)(base + O_CSRD);
    int*   p_cnt  = (int*)(base + O_CNT);
    int*   p_off  = (int*)(base + O_OFF);
    int*   p_cur  = (int*)(base + O_CUR);
    float* p_expv = (float*)(base + O_EXPV);
    float* p_ivz  = (float*)(base + O_IVZ);
    float* p_h1   = (float*)(base + O_H1);
    float* p_s1s  = (float*)(base + O_S1S);
    float* p_s1d  = (float*)(base + O_S1D);
    float* p_h1c  = (float*)(base + O_H1C);
    float* p_s2s  = (float*)(base + O_S2S);
    float* p_s2d  = (float*)(base + O_S2D);
    float* p_ws   = (float*)(base + O_WS);
    float* p_wd   = (float*)(base + O_WD);
    float* p_w2c  = (float*)(base + O_W2C);
    float* p_bc   = (float*)(base + O_BC);
    float* p_agg  = (float*)(base + O_AGG);
    int*   p_src  = (int*)(base + O_SRC);
    int*   p_dst  = (int*)(base + O_DST);
    float* p_h2p  = (float*)(base + O_H2P);

    // CSR build
    cudaMemsetAsync(p_cnt, 0, 2 * N_ * sizeof(int));
    k_prep<<<(135232 + 255) / 256, 256>>>(W2, a2s, a2d, b2, p_w2c, p_ws, p_wd, p_bc);
    k_cvt<<<dim3((E_ + 255) / 256, 2), 256>>>(eia, eib, p_src, p_dst, p_cnt);
    k_scan<<<2, 1024>>>(p_cnt, p_off, p_cur);
    k_scatter<<<(2 * E_ + 255) / 256, 256>>>(p_src, p_dst, p_cur, p_csr, p_csrd);

    // layer 1
    k_sgemm<256><<<dim3(157, 1, 2), 256>>>(x, W1, p_h1, N_, 128);
    k_scores<16><<<dim3((N_ + 7) / 8, 2), 256>>>(p_h1, a1s, a1d, p_s1s, p_s1d);
    k_expv<<<dim3(E_ * 8 / 256, 2), 256>>>(p_csr, p_csrd, p_s1s, p_s1d, p_expv);
    k_z<<<dim3((N_ + 7) / 8, 2), 256>>>(p_off, p_cnt, p_expv, p_ivz);
    k_gat1<<<(N_ + 7) / 8, 256>>>(p_off, p_cnt, p_csr, p_expv, p_ivz, p_h1, b1, p_h1c);

    // layer 2 (aggregation in h1c domain, GEMM deferred)
    k_scores2<<<(N_ + 7) / 8, 256>>>(p_h1c, p_ws, p_wd, p_s2s, p_s2d);
    k_expv<<<dim3(E_ * 8 / 256, 2), 256>>>(p_csr, p_csrd, p_s2s, p_s2d, p_expv);
    k_z<<<dim3((N_ + 7) / 8, 2), 256>>>(p_off, p_cnt, p_expv, p_ivz);
    k_gat2<<<(N_ + 7) / 8, 256>>>(p_off, p_cnt, p_csr, p_expv, p_ivz, p_h1c, p_agg);
    k_gemm3<<<157, 256>>>(p_agg, p_w2c, p_h2p);

    // classifier
    k_classifier<<<(N_ * 32 + 255) / 256, 256>>>(p_h2p, p_bc, Wc1, bc1, Wc2, bc2, out);
}

// round 6
// speedup vs baseline: 1.2054x; 1.2054x over previous
#include <cuda_runtime.h>
#include <cuda_bf16.h>
#include <cstdint>
#include <cstddef>

#define N_ 20000
#define E_ 640000
#define MB (1048576ull)

// ---------------- scratch layout ----------------
static const size_t O_CSR  = 0;                // int[2E] 5.12MB
static const size_t O_CNT  = 6*MB;
static const size_t O_OFF  = 7*MB;
static const size_t O_CUR  = 8*MB;
static const size_t O_XB   = 9*MB;             // bf16[20000*512] hi|lo blocks, 20.5MB
static const size_t O_H1   = 30*MB;            // fp32[20000*256] 20.5MB
static const size_t O_S1S  = 51*MB;            // fp32[2*N*8] (2MB slots)
static const size_t O_S1D  = 53*MB;
static const size_t O_H1C  = 55*MB;            // fp32[N*128] 10.2MB
static const size_t O_S2S  = 66*MB;
static const size_t O_S2D  = 68*MB;
static const size_t O_WS   = 70*MB;            // fp32[2048]
static const size_t O_WD   = 70*MB + 16384;
static const size_t O_BC   = 70*MB + 32768;
static const size_t O_WT1  = 71*MB;            // bf16[256*768] 393KB
static const size_t O_WT2  = 72*MB;            // bf16[64*6144] 786KB
static const size_t O_AGGB = 73*MB;            // bf16[20000*4096] hi|lo, 164MB -> 73..238
static const size_t O_SRC  = 73*MB;            // int[2E] temp (dead before AGGB written)
static const size_t O_DST  = 79*MB;            // int[2E] temp
static const size_t O_H2P  = 238*MB;           // fp32[N*64]
static const size_t SCRATCH_BYTES = 244*MB;

__device__ __align__(1024) unsigned char g_scratch[SCRATCH_BYTES];

__device__ __forceinline__ float eluf(float x) { return x > 0.f ? x : expm1f(x); }
__device__ __forceinline__ float lrelu(float x) { return x > 0.f ? x : 0.2f * x; }

__device__ __forceinline__ void hl_split(float x, uint16_t& h, uint16_t& l) {
    __nv_bfloat16 hb = __float2bfloat16(x);
    h = __bfloat16_as_ushort(hb);
    l = __bfloat16_as_ushort(__float2bfloat16(x - __bfloat162float(hb)));
}

// ================= mma.sync bf16 GEMM =================
// C[rows x (gridDim.y*64)] = A[rows x 2K] (hi|lo blocks) @ B[64*gy x 3K]^T (whi|whi|wlo)
// HA = K/64 (chunks per block). NCHUNK = 3*HA. LDA = 2*K halves, LDB = 3*K halves.
template<int HA, int LDA, int LDB>
__global__ void __launch_bounds__(256) k_mmagemm(
    const uint16_t* __restrict__ A, const uint16_t* __restrict__ B,
    float* __restrict__ C, int nrows, int ldc)
{
    __shared__ uint16_t As[128 * 72];
    __shared__ uint16_t Bs[64 * 72];
    const int NCHUNK = 3 * HA;
    int tid = threadIdx.x;
    int wm = tid >> 5, lane = tid & 31;
    int g = lane >> 2, t = lane & 3;
    int rowBase = blockIdx.x * 128;
    int colBase = blockIdx.y * 64;

    float c[8][4];
#pragma unroll
    for (int i = 0; i < 8; i++)
#pragma unroll
        for (int j = 0; j < 4; j++) c[i][j] = 0.f;

    for (int ch = 0; ch < NCHUNK; ch++) {
        int aoff = (ch >= 2 * HA) ? (ch - 2 * HA) : ch;   // re-read hi block 3rd pass
        // load A chunk [128 x 64 halves]
#pragma unroll
        for (int it = 0; it < 4; it++) {
            int s = it * 256 + tid;       // 0..1023
            int row = s >> 3, k8 = s & 7;
            uint4 v = make_uint4(0u, 0u, 0u, 0u);
            int gr = rowBase + row;
            if (gr < nrows)
                v = *(const uint4*)(A + (size_t)gr * LDA + aoff * 64 + k8 * 8);
            *(uint4*)&As[row * 72 + k8 * 8] = v;
        }
        // load B chunk [64 x 64 halves]
#pragma unroll
        for (int it = 0; it < 2; it++) {
            int s = it * 256 + tid;       // 0..511
            int row = s >> 3, k8 = s & 7;
            uint4 v = *(const uint4*)(B + (size_t)(colBase + row) * LDB + ch * 64 + k8 * 8);
            *(uint4*)&Bs[row * 72 + k8 * 8] = v;
        }
        __syncthreads();
#pragma unroll
        for (int ks = 0; ks < 4; ks++) {
            int k0 = ks * 16;
            uint32_t a0 = *(const uint32_t*)&As[(wm * 16 + g) * 72 + k0 + 2 * t];
            uint32_t a1 = *(const uint32_t*)&As[(wm * 16 + g + 8) * 72 + k0 + 2 * t];
            uint32_t a2 = *(const uint32_t*)&As[(wm * 16 + g) * 72 + k0 + 2 * t + 8];
            uint32_t a3 = *(const uint32_t*)&As[(wm * 16 + g + 8) * 72 + k0 + 2 * t + 8];
#pragma unroll
            for (int nf = 0; nf < 8; nf++) {
                uint32_t b0 = *(const uint32_t*)&Bs[(nf * 8 + g) * 72 + k0 + 2 * t];
                uint32_t b1 = *(const uint32_t*)&Bs[(nf * 8 + g) * 72 + k0 + 2 * t + 8];
                asm volatile(
                    "mma.sync.aligned.m16n8k16.row.col.f32.bf16.bf16.f32 "
                    "{%0,%1,%2,%3}, {%4,%5,%6,%7}, {%8,%9}, {%0,%1,%2,%3};"
                    : "+f"(c[nf][0]), "+f"(c[nf][1]), "+f"(c[nf][2]), "+f"(c[nf][3])
                    : "r"(a0), "r"(a1), "r"(a2), "r"(a3), "r"(b0), "r"(b1));
            }
        }
        __syncthreads();
    }
    int r0 = rowBase + wm * 16 + g;
    int r1 = r0 + 8;
#pragma unroll
    for (int nf = 0; nf < 8; nf++) {
        int col = colBase + nf * 8 + 2 * t;
        if (r0 < nrows) *(float2*)(C + (size_t)r0 * ldc + col) = make_float2(c[nf][0], c[nf][1]);
        if (r1 < nrows) *(float2*)(C + (size_t)r1 * ldc + col) = make_float2(c[nf][2], c[nf][3]);
    }
}

// ================= graph preprocessing =================
__global__ void k_cvt(const void* pa, const void* pb, int* src, int* dst, int* cnt) {
    int t = blockIdx.y;
    const void* p = t ? pb : pa;
    unsigned ov = ((const unsigned*)p)[1 + 2 * (threadIdx.x & 31)];
    int is64 = __all_sync(0xffffffffu, ov == 0u);
    int i = blockIdx.x * blockDim.x + threadIdx.x;
    if (i >= E_) return;
    int s, d;
    if (is64) {
        const long long* q = (const long long*)p;
        s = (int)q[i]; d = (int)q[E_ + i];
    } else {
        const int* q = (const int*)p;
        s = q[i]; d = q[E_ + i];
    }
    src[t * E_ + i] = s;
    dst[t * E_ + i] = d;
    atomicAdd(&cnt[t * N_ + d], 1);
}

__global__ void k_scan(const int* __restrict__ cnt, int* __restrict__ offs, int* __restrict__ cur)
{
    int t = blockIdx.x;
    const int4* c4 = (const int4*)(cnt + t * N_);
    int4* o4 = (int4*)(offs + t * N_);
    int4* q4 = (int4*)(cur + t * N_);
    __shared__ int wsum[32];
    __shared__ int sbase;
    int tid = threadIdx.x, lane = tid & 31, w = tid >> 5;
    if (tid == 0) sbase = 0;
    __syncthreads();
    const int N4 = N_ / 4;
    for (int i0 = 0; i0 < N4; i0 += 1024) {
        int i = i0 + tid;
        int4 c = make_int4(0, 0, 0, 0);
        if (i < N4) c = c4[i];
        int s = c.x + c.y + c.z + c.w;
        int x = s;
#pragma unroll
        for (int ofs = 1; ofs < 32; ofs <<= 1) {
            int y = __shfl_up_sync(0xffffffffu, x, ofs);
            if (lane >= ofs) x += y;
        }
        if (lane == 31) wsum[w] = x;
        __syncthreads();
        if (w == 0) {
            int v = wsum[lane];
#pragma unroll
            for (int ofs = 1; ofs < 32; ofs <<= 1) {
                int y = __shfl_up_sync(0xffffffffu, v, ofs);
                if (lane >= ofs) v += y;
            }
            wsum[lane] = v;
        }
        __syncthreads();
        int excl = sbase + (w ? wsum[w - 1] : 0) + x - s;
        if (i < N4) {
            int4 r;
            r.x = excl; r.y = excl + c.x; r.z = r.y + c.y; r.w = r.z + c.z;
            o4[i] = r; q4[i] = r;
        }
        __syncthreads();
        if (tid == 0) sbase += wsum[31];
        __syncthreads();
    }
}

__global__ void k_scatter(const int* __restrict__ src, const int* __restrict__ dst,
                          int* __restrict__ cur, int* __restrict__ csr)
{
    int i = blockIdx.x * blockDim.x + threadIdx.x;
    if (i >= 2 * E_) return;
    int t = (i >= E_) ? 1 : 0;
    int e = i - t * E_;
    int s = src[t * E_ + e], d = dst[t * E_ + e];
    int pos = atomicAdd(&cur[t * N_ + d], 1);
    csr[(size_t)t * E_ + pos] = s;
}

// precompute: Wt1/Wt2 bf16 blocks (whi|whi|wlo), score projections, combined bias
__global__ void k_prep(const float* __restrict__ W2, const float* __restrict__ a2s,
                       const float* __restrict__ a2d, const float* __restrict__ b2,
                       const float* __restrict__ W1,
                       uint16_t* __restrict__ Wt1, uint16_t* __restrict__ Wt2,
                       float* __restrict__ ws, float* __restrict__ wd, float* __restrict__ bc)
{
    int i = blockIdx.x * blockDim.x + threadIdx.x;
    if (i < 131072) {
        // Wt2[n][k], k = t*1024 + h*128 + c, val = W2[t][c*512+h*64+n]/16
        int n = i & 63, k = i >> 6;
        int t = k >> 10, r = k & 1023, h = r >> 7, cc = r & 127;
        float wv = W2[t * 65536 + cc * 512 + h * 64 + n] * 0.0625f;
        uint16_t hh, ll; hl_split(wv, hh, ll);
        uint16_t* p = Wt2 + (size_t)n * 6144 + k;
        p[0] = hh; p[2048] = hh; p[4096] = ll;
    } else if (i < 196608) {
        // Wt1[np][k], np = t*128+n, val = W1[t][k*128+n], k=0..255
        int j = i - 131072;
        int np = j & 255, k = j >> 8;
        int t = np >> 7, n = np & 127;
        float wv = W1[t * 32768 + k * 128 + n];
        uint16_t hh, ll; hl_split(wv, hh, ll);
        uint16_t* p = Wt1 + (size_t)np * 768 + k;
        p[0] = hh; p[256] = hh; p[512] = ll;
    } else if (i < 198656) {
        int j = i - 196608;
        int t = j >> 10, r = j & 1023, h = r >> 7, cc = r & 127;
        const float* wrow = W2 + t * 65536 + cc * 512 + h * 64;
        const float* av = a2s + t * 512 + h * 64;
        float acc = 0.f;
        for (int o = 0; o < 64; o++) acc += wrow[o] * av[o];
        ws[j] = acc;
    } else if (i < 200704) {
        int j = i - 198656;
        int t = j >> 10, r = j & 1023, h = r >> 7, cc = r & 127;
        const float* wrow = W2 + t * 65536 + cc * 512 + h * 64;
        const float* av = a2d + t * 512 + h * 64;
        float acc = 0.f;
        for (int o = 0; o < 64; o++) acc += wrow[o] * av[o];
        wd[j] = acc;
    } else if (i < 200768) {
        int o = i - 200704;
        bc[o] = 0.5f * (b2[o] + b2[64 + o]);
    }
}

// X fp32 -> bf16 hi|lo blocks: xb[row][0..255]=hi, [256..511]=lo
__global__ void k_cvtx(const float* __restrict__ x, uint16_t* __restrict__ xb) {
    int i = blockIdx.x * blockDim.x + threadIdx.x;   // float4 index
    if (i >= N_ * 64) return;
    int row = i >> 6, k4 = (i & 63) << 2;
    float4 v = ((const float4*)x)[i];
    uint16_t h0, l0, h1, l1, h2, l2, h3, l3;
    hl_split(v.x, h0, l0); hl_split(v.y, h1, l1);
    hl_split(v.z, h2, l2); hl_split(v.w, h3, l3);
    uint2 hi, lo;
    hi.x = (uint32_t)h0 | ((uint32_t)h1 << 16);
    hi.y = (uint32_t)h2 | ((uint32_t)h3 << 16);
    lo.x = (uint32_t)l0 | ((uint32_t)l1 << 16);
    lo.y = (uint32_t)l2 | ((uint32_t)l3 << 16);
    *(uint2*)(xb + (size_t)row * 512 + k4) = hi;
    *(uint2*)(xb + (size_t)row * 512 + 256 + k4) = lo;
}

// ---------------- layer-1 scores: warp per (node, type) ----------------
__global__ void k_scores1(const float* __restrict__ h1,
                          const float* __restrict__ a_src, const float* __restrict__ a_dst,
                          float* __restrict__ ss, float* __restrict__ sd)
{
    int node = blockIdx.x * 8 + (threadIdx.x >> 5);
    int lane = threadIdx.x & 31;
    int t = blockIdx.y;
    if (node >= N_) return;
    const float* hr = h1 + (size_t)node * 256 + t * 128;
    float4 v = *(const float4*)(hr + lane * 4);
    float4 w = *(const float4*)(a_src + t * 128 + lane * 4);
    float4 u = *(const float4*)(a_dst + t * 128 + lane * 4);
    float ps = v.x * w.x + v.y * w.y + v.z * w.z + v.w * w.w;
    float pd = v.x * u.x + v.y * u.y + v.z * u.z + v.w * u.w;
    ps += __shfl_xor_sync(0xffffffffu, ps, 1);
    ps += __shfl_xor_sync(0xffffffffu, ps, 2);
    pd += __shfl_xor_sync(0xffffffffu, pd, 1);
    pd += __shfl_xor_sync(0xffffffffu, pd, 2);
    if ((lane & 3) == 0) {
        ss[t * N_ * 8 + node * 8 + (lane >> 2)] = ps;
        sd[t * N_ * 8 + node * 8 + (lane >> 2)] = pd;
    }
}

// ---------------- layer-1 GAT aggregate (fused z + gather, chunked) ----------------
__global__ void __launch_bounds__(256) k_gat1(
    const int* __restrict__ offs, const int* __restrict__ cnt, const int* __restrict__ csr,
    const float* __restrict__ s1s, const float* __restrict__ s1d,
    const float* __restrict__ h1, const float* __restrict__ b1,
    float* __restrict__ h1c)
{
    __shared__ float sa[8][256];
    int w = threadIdx.x >> 5, lane = threadIdx.x & 31;
    int d = blockIdx.x * 8 + w;
    if (d >= N_) return;
    int hd = lane >> 2;
    float4 acc = make_float4(0.f, 0.f, 0.f, 0.f);
    for (int t = 0; t < 2; t++) {
        int beg = offs[t * N_ + d], n = cnt[t * N_ + d];
        const float* ss = s1s + (size_t)t * N_ * 8;
        const float4* sdp = (const float4*)(s1d + ((size_t)t * N_ + d) * 8);
        float4 sd0 = sdp[0], sd1 = sdp[1];
        float sdv[8] = {sd0.x, sd0.y, sd0.z, sd0.w, sd1.x, sd1.y, sd1.z, sd1.w};
        const int* cs = csr + (size_t)t * E_ + beg;
        float zp[8];
#pragma unroll
        for (int k = 0; k < 8; k++) zp[k] = 0.f;
        for (int c0 = 0; c0 < n; c0 += 32) {
            int m = n - c0; if (m > 32) m = 32;
            if (lane < m) {
                int sL = cs[c0 + lane];
                float4 a0 = *(const float4*)(ss + (size_t)sL * 8);
                float4 a1 = *(const float4*)(ss + (size_t)sL * 8 + 4);
                zp[0] += __expf(lrelu(a0.x + sdv[0]));
                zp[1] += __expf(lrelu(a0.y + sdv[1]));
                zp[2] += __expf(lrelu(a0.z + sdv[2]));
                zp[3] += __expf(lrelu(a0.w + sdv[3]));
                zp[4] += __expf(lrelu(a1.x + sdv[4]));
                zp[5] += __expf(lrelu(a1.y + sdv[5]));
                zp[6] += __expf(lrelu(a1.z + sdv[6]));
                zp[7] += __expf(lrelu(a1.w + sdv[7]));
            }
        }
        float izv[8];
#pragma unroll
        for (int k = 0; k < 8; k++) {
            float v = zp[k];
            v += __shfl_xor_sync(0xffffffffu, v, 1);
            v += __shfl_xor_sync(0xffffffffu, v, 2);
            v += __shfl_xor_sync(0xffffffffu, v, 4);
            v += __shfl_xor_sync(0xffffffffu, v, 8);
            v += __shfl_xor_sync(0xffffffffu, v, 16);
            izv[k] = 1.f / v;
        }
        for (int c0 = 0; c0 < n; c0 += 32) {
            int m = n - c0; if (m > 32) m = 32;
            int sL = 0;
            if (lane < m) {
                sL = cs[c0 + lane];
                float4 a0 = *(const float4*)(ss + (size_t)sL * 8);
                float4 a1 = *(const float4*)(ss + (size_t)sL * 8 + 4);
                float4 e0, e1;
                e0.x = __expf(lrelu(a0.x + sdv[0])) * izv[0];
                e0.y = __expf(lrelu(a0.y + sdv[1])) * izv[1];
                e0.z = __expf(lrelu(a0.z + sdv[2])) * izv[2];
                e0.w = __expf(lrelu(a0.w + sdv[3])) * izv[3];
                e1.x = __expf(lrelu(a1.x + sdv[4])) * izv[4];
                e1.y = __expf(lrelu(a1.y + sdv[5])) * izv[5];
                e1.z = __expf(lrelu(a1.z + sdv[6])) * izv[6];
                e1.w = __expf(lrelu(a1.w + sdv[7])) * izv[7];
                *(float4*)&sa[w][lane * 8] = e0;
                *(float4*)&sa[w][lane * 8 + 4] = e1;
            }
            __syncwarp();
#pragma unroll
            for (int j = 0; j < 32; j++) {
                if (j < m) {
                    int sj = __shfl_sync(0xffffffffu, sL, j);
                    float a = sa[w][j * 8 + hd];
                    float4 v = *(const float4*)(h1 + (size_t)sj * 256 + t * 128 + lane * 4);
                    acc.x = fmaf(a, v.x, acc.x);
                    acc.y = fmaf(a, v.y, acc.y);
                    acc.z = fmaf(a, v.z, acc.z);
                    acc.w = fmaf(a, v.w, acc.w);
                }
            }
            __syncwarp();
        }
    }
    float4 bb0 = *(const float4*)(b1 + lane * 4);
    float4 bb1 = *(const float4*)(b1 + 128 + lane * 4);
    float4 r;
    r.x = eluf(0.5f * (acc.x + bb0.x + bb1.x));
    r.y = eluf(0.5f * (acc.y + bb0.y + bb1.y));
    r.z = eluf(0.5f * (acc.z + bb0.z + bb1.z));
    r.w = eluf(0.5f * (acc.w + bb0.w + bb1.w));
    *(float4*)(h1c + (size_t)d * 128 + lane * 4) = r;
}

// ---------------- layer-2 scores from projected vectors ----------------
__global__ void k_scores2(const float* __restrict__ h1c,
                          const float* __restrict__ ws, const float* __restrict__ wd,
                          float* __restrict__ s2s, float* __restrict__ s2d)
{
    int node = blockIdx.x * 8 + (threadIdx.x >> 5);
    int lane = threadIdx.x & 31;
    if (node >= N_) return;
    float4 v = *(const float4*)(h1c + (size_t)node * 128 + lane * 4);
#pragma unroll
    for (int c = 0; c < 16; c++) {
        float4 w = *(const float4*)(ws + c * 128 + lane * 4);
        float p = v.x * w.x + v.y * w.y + v.z * w.z + v.w * w.w;
        p += __shfl_xor_sync(0xffffffffu, p, 16);
        p += __shfl_xor_sync(0xffffffffu, p, 8);
        p += __shfl_xor_sync(0xffffffffu, p, 4);
        p += __shfl_xor_sync(0xffffffffu, p, 2);
        p += __shfl_xor_sync(0xffffffffu, p, 1);
        float4 u = *(const float4*)(wd + c * 128 + lane * 4);
        float q = v.x * u.x + v.y * u.y + v.z * u.z + v.w * u.w;
        q += __shfl_xor_sync(0xffffffffu, q, 16);
        q += __shfl_xor_sync(0xffffffffu, q, 8);
        q += __shfl_xor_sync(0xffffffffu, q, 4);
        q += __shfl_xor_sync(0xffffffffu, q, 2);
        q += __shfl_xor_sync(0xffffffffu, q, 1);
        if (lane == 0) {
            s2s[(c >> 3) * N_ * 8 + node * 8 + (c & 7)] = p;
            s2d[(c >> 3) * N_ * 8 + node * 8 + (c & 7)] = q;
        }
    }
}

// ---------------- layer-2 aggregate -> bf16 hi|lo agg matrix ----------------
__global__ void __launch_bounds__(256) k_gat2(
    const int* __restrict__ offs, const int* __restrict__ cnt, const int* __restrict__ csr,
    const float* __restrict__ s2s, const float* __restrict__ s2d,
    const float* __restrict__ h1c, uint16_t* __restrict__ aggb)
{
    __shared__ float sa[8][256];
    int w = threadIdx.x >> 5, lane = threadIdx.x & 31;
    int d = blockIdx.x * 8 + w;
    if (d >= N_) return;
    for (int t = 0; t < 2; t++) {
        int beg = offs[t * N_ + d], n = cnt[t * N_ + d];
        const float* ss = s2s + (size_t)t * N_ * 8;
        const float4* sdp = (const float4*)(s2d + ((size_t)t * N_ + d) * 8);
        float4 sd0 = sdp[0], sd1 = sdp[1];
        float sdv[8] = {sd0.x, sd0.y, sd0.z, sd0.w, sd1.x, sd1.y, sd1.z, sd1.w};
        const int* cs = csr + (size_t)t * E_ + beg;
        float zp[8];
#pragma unroll
        for (int k = 0; k < 8; k++) zp[k] = 0.f;
        for (int c0 = 0; c0 < n; c0 += 32) {
            int m = n - c0; if (m > 32) m = 32;
            if (lane < m) {
                int sL = cs[c0 + lane];
                float4 a0 = *(const float4*)(ss + (size_t)sL * 8);
                float4 a1 = *(const float4*)(ss + (size_t)sL * 8 + 4);
                zp[0] += __expf(lrelu(a0.x + sdv[0]));
                zp[1] += __expf(lrelu(a0.y + sdv[1]));
                zp[2] += __expf(lrelu(a0.z + sdv[2]));
                zp[3] += __expf(lrelu(a0.w + sdv[3]));
                zp[4] += __expf(lrelu(a1.x + sdv[4]));
                zp[5] += __expf(lrelu(a1.y + sdv[5]));
                zp[6] += __expf(lrelu(a1.z + sdv[6]));
                zp[7] += __expf(lrelu(a1.w + sdv[7]));
            }
        }
        float izv[8];
#pragma unroll
        for (int k = 0; k < 8; k++) {
            float v = zp[k];
            v += __shfl_xor_sync(0xffffffffu, v, 1);
            v += __shfl_xor_sync(0xffffffffu, v, 2);
            v += __shfl_xor_sync(0xffffffffu, v, 4);
            v += __shfl_xor_sync(0xffffffffu, v, 8);
            v += __shfl_xor_sync(0xffffffffu, v, 16);
            izv[k] = 1.f / v;
        }
        float4 acc[8];
#pragma unroll
        for (int h = 0; h < 8; h++) acc[h] = make_float4(0.f, 0.f, 0.f, 0.f);
        for (int c0 = 0; c0 < n; c0 += 32) {
            int m = n - c0; if (m > 32) m = 32;
            int sL = 0;
            if (lane < m) {
                sL = cs[c0 + lane];
                float4 a0 = *(const float4*)(ss + (size_t)sL * 8);
                float4 a1 = *(const float4*)(ss + (size_t)sL * 8 + 4);
                float4 e0, e1;
                e0.x = __expf(lrelu(a0.x + sdv[0])) * izv[0];
                e0.y = __expf(lrelu(a0.y + sdv[1])) * izv[1];
                e0.z = __expf(lrelu(a0.z + sdv[2])) * izv[2];
                e0.w = __expf(lrelu(a0.w + sdv[3])) * izv[3];
                e1.x = __expf(lrelu(a1.x + sdv[4])) * izv[4];
                e1.y = __expf(lrelu(a1.y + sdv[5])) * izv[5];
                e1.z = __expf(lrelu(a1.z + sdv[6])) * izv[6];
                e1.w = __expf(lrelu(a1.w + sdv[7])) * izv[7];
                *(float4*)&sa[w][lane * 8] = e0;
                *(float4*)&sa[w][lane * 8 + 4] = e1;
            }
            __syncwarp();
#pragma unroll
            for (int j = 0; j < 32; j++) {
                if (j < m) {
                    int sj = __shfl_sync(0xffffffffu, sL, j);
                    float4 a0 = *(const float4*)&sa[w][j * 8];
                    float4 a1 = *(const float4*)&sa[w][j * 8 + 4];
                    float4 v = *(const float4*)(h1c + (size_t)sj * 128 + lane * 4);
                    acc[0].x = fmaf(a0.x, v.x, acc[0].x); acc[0].y = fmaf(a0.x, v.y, acc[0].y);
                    acc[0].z = fmaf(a0.x, v.z, acc[0].z); acc[0].w = fmaf(a0.x, v.w, acc[0].w);
                    acc[1].x = fmaf(a0.y, v.x, acc[1].x); acc[1].y = fmaf(a0.y, v.y, acc[1].y);
                    acc[1].z = fmaf(a0.y, v.z, acc[1].z); acc[1].w = fmaf(a0.y, v.w, acc[1].w);
                    acc[2].x = fmaf(a0.z, v.x, acc[2].x); acc[2].y = fmaf(a0.z, v.y, acc[2].y);
                    acc[2].z = fmaf(a0.z, v.z, acc[2].z); acc[2].w = fmaf(a0.z, v.w, acc[2].w);
                    acc[3].x = fmaf(a0.w, v.x, acc[3].x); acc[3].y = fmaf(a0.w, v.y, acc[3].y);
                    acc[3].z = fmaf(a0.w, v.z, acc[3].z); acc[3].w = fmaf(a0.w, v.w, acc[3].w);
                    acc[4].x = fmaf(a1.x, v.x, acc[4].x); acc[4].y = fmaf(a1.x, v.y, acc[4].y);
                    acc[4].z = fmaf(a1.x, v.z, acc[4].z); acc[4].w = fmaf(a1.x, v.w, acc[4].w);
                    acc[5].x = fmaf(a1.y, v.x, acc[5].x); acc[5].y = fmaf(a1.y, v.y, acc[5].y);
                    acc[5].z = fmaf(a1.y, v.z, acc[5].z); acc[5].w = fmaf(a1.y, v.w, acc[5].w);
                    acc[6].x = fmaf(a1.z, v.x, acc[6].x); acc[6].y = fmaf(a1.z, v.y, acc[6].y);
                    acc[6].z = fmaf(a1.z, v.z, acc[6].z); acc[6].w = fmaf(a1.z, v.w, acc[6].w);
                    acc[7].x = fmaf(a1.w, v.x, acc[7].x); acc[7].y = fmaf(a1.w, v.y, acc[7].y);
                    acc[7].z = fmaf(a1.w, v.z, acc[7].z); acc[7].w = fmaf(a1.w, v.w, acc[7].w);
                }
            }
            __syncwarp();
        }
        // write hi|lo blocks: k = t*1024 + h*128 + lane*4, hi at k, lo at 2048+k
#pragma unroll
        for (int h = 0; h < 8; h++) {
            uint16_t h0, l0, h1v, l1, h2, l2, h3, l3;
            hl_split(acc[h].x, h0, l0); hl_split(acc[h].y, h1v, l1);
            hl_split(acc[h].z, h2, l2); hl_split(acc[h].w, h3, l3);
            uint2 hi, lo;
            hi.x = (uint32_t)h0 | ((uint32_t)h1v << 16);
            hi.y = (uint32_t)h2 | ((uint32_t)h3 << 16);
            lo.x = (uint32_t)l0 | ((uint32_t)l1 << 16);
            lo.y = (uint32_t)l2 | ((uint32_t)l3 << 16);
            int k = t * 1024 + h * 128 + lane * 4;
            *(uint2*)(aggb + (size_t)d * 4096 + k) = hi;
            *(uint2*)(aggb + (size_t)d * 4096 + 2048 + k) = lo;
        }
    }
}

// ---------------- classifier (bias + ELU fused) ----------------
__global__ void k_classifier(const float* __restrict__ h, const float* __restrict__ bc,
                             const float* __restrict__ Wc1, const float* __restrict__ bc1,
                             const float* __restrict__ Wc2, const float* __restrict__ bc2,
                             float* __restrict__ out)
{
    int wid = (blockIdx.x * blockDim.x + threadIdx.x) >> 5;
    int lane = threadIdx.x & 31;
    if (wid >= N_) return;
    const float* hr = h + (size_t)wid * 64;
    float acc = bc1[lane];
#pragma unroll
    for (int c = 0; c < 64; c++) {
        float hv = eluf(__ldg(hr + c) + __ldg(bc + c));
        acc = fmaf(hv, Wc1[c * 32 + lane], acc);
    }
    acc = fmaxf(acc, 0.f);
    float p0 = acc * Wc2[lane * 2];
    float p1 = acc * Wc2[lane * 2 + 1];
#pragma unroll
    for (int o = 16; o >= 1; o >>= 1) {
        p0 += __shfl_xor_sync(0xffffffffu, p0, o);
        p1 += __shfl_xor_sync(0xffffffffu, p1, o);
    }
    if (lane == 0) {
        out[wid * 2 + 0] = p0 + bc2[0];
        out[wid * 2 + 1] = p1 + bc2[1];
    }
}

// ---------------- launch ----------------
extern "C" void kernel_launch(void* const* d_in, const int* in_sizes, int n_in,
                              void* d_out, int out_size)
{
    const float* x    = (const float*)d_in[0];
    const void*  eia  = d_in[1];
    const void*  eib  = d_in[2];
    const float* W1   = (const float*)d_in[3];
    const float* a1s  = (const float*)d_in[4];
    const float* a1d  = (const float*)d_in[5];
    const float* b1   = (const float*)d_in[6];
    const float* W2   = (const float*)d_in[7];
    const float* a2s  = (const float*)d_in[8];
    const float* a2d  = (const float*)d_in[9];
    const float* b2   = (const float*)d_in[10];
    const float* Wc1  = (const float*)d_in[11];
    const float* bc1  = (const float*)d_in[12];
    const float* Wc2  = (const float*)d_in[13];
    const float* bc2  = (const float*)d_in[14];
    float* out = (float*)d_out;

    void* basev = nullptr;
    cudaGetSymbolAddress(&basev, g_scratch);
    unsigned char* base = (unsigned char*)basev;

    int*      p_csr  = (int*)(base + O_CSR);
    int*      p_cnt  = (int*)(base + O_CNT);
    int*      p_off  = (int*)(base + O_OFF);
    int*      p_cur  = (int*)(base + O_CUR);
    uint16_t* p_xb   = (uint16_t*)(base + O_XB);
    float*    p_h1   = (float*)(base + O_H1);
    float*    p_s1s  = (float*)(base + O_S1S);
    float*    p_s1d  = (float*)(base + O_S1D);
    float*    p_h1c  = (float*)(base + O_H1C);
    float*    p_s2s  = (float*)(base + O_S2S);
    float*    p_s2d  = (float*)(base + O_S2D);
    float*    p_ws   = (float*)(base + O_WS);
    float*    p_wd   = (float*)(base + O_WD);
    float*    p_bc   = (float*)(base + O_BC);
    uint16_t* p_wt1  = (uint16_t*)(base + O_WT1);
    uint16_t* p_wt2  = (uint16_t*)(base + O_WT2);
    uint16_t* p_aggb = (uint16_t*)(base + O_AGGB);
    int*      p_src  = (int*)(base + O_SRC);
    int*      p_dst  = (int*)(base + O_DST);
    float*    p_h2p  = (float*)(base + O_H2P);

    // CSR build + weight prep
    cudaMemsetAsync(p_cnt, 0, 2 * N_ * sizeof(int));
    k_prep<<<(200768 + 255) / 256, 256>>>(W2, a2s, a2d, b2, W1, p_wt1, p_wt2, p_ws, p_wd, p_bc);
    k_cvt<<<dim3((E_ + 255) / 256, 2), 256>>>(eia, eib, p_src, p_dst, p_cnt);
    k_cvtx<<<(N_ * 64 + 255) / 256, 256>>>(x, p_xb);
    k_scan<<<2, 1024>>>(p_cnt, p_off, p_cur);
    k_scatter<<<(2 * E_ + 255) / 256, 256>>>(p_src, p_dst, p_cur, p_csr);

    // layer 1: mma GEMM [20000x512(hi|lo)] @ [256x768]^T -> h1[20000x256]
    k_mmagemm<4, 512, 768><<<dim3(157, 4), 256>>>(p_xb, p_wt1, p_h1, N_, 256);
    k_scores1<<<dim3((N_ + 7) / 8, 2), 256>>>(p_h1, a1s, a1d, p_s1s, p_s1d);
    k_gat1<<<(N_ + 7) / 8, 256>>>(p_off, p_cnt, p_csr, p_s1s, p_s1d, p_h1, b1, p_h1c);

    // layer 2: scores -> aggregate (bf16 hi|lo) -> mma GEMM [20000x4096] @ [64x6144]^T
    k_scores2<<<(N_ + 7) / 8, 256>>>(p_h1c, p_ws, p_wd, p_s2s, p_s2d);
    k_gat2<<<(N_ + 7) / 8, 256>>>(p_off, p_cnt, p_csr, p_s2s, p_s2d, p_h1c, p_aggb);
    k_mmagemm<32, 4096, 6144><<<dim3(157, 1), 256>>>(p_aggb, p_wt2, p_h2p, N_, 64);

    // classifier
    k_classifier<<<(N_ * 32 + 255) / 256, 256>>>(p_h2p, p_bc, Wc1, bc1, Wc2, bc2, out);
}

// round 7
// speedup vs baseline: 1.4416x; 1.1959x over previous
#include <cuda_runtime.h>
#include <cuda_bf16.h>
#include <cstdint>
#include <cstddef>

#define N_ 20000
#define E_ 640000
#define MB (1048576ull)

// ---------------- scratch layout ----------------
static const size_t O_CSR  = 0;                // int[2E] 5.12MB
static const size_t O_CNT  = 6*MB;
static const size_t O_OFF  = 7*MB;
static const size_t O_CUR  = 8*MB;
static const size_t O_XB   = 9*MB;             // bf16[20000*512] hi|lo, 20.5MB
static const size_t O_H1   = 30*MB;            // fp32[20000*256] 20.5MB
static const size_t O_S1S  = 51*MB;            // fp32[2*N*8]
static const size_t O_S1D  = 53*MB;
static const size_t O_H1C  = 55*MB;            // fp32[N*128] 10.2MB
static const size_t O_S2S  = 66*MB;
static const size_t O_S2D  = 68*MB;
static const size_t O_WS   = 70*MB;            // fp32[2048]
static const size_t O_WD   = 70*MB + 16384;
static const size_t O_BC   = 70*MB + 32768;
static const size_t O_WT1  = 71*MB;            // bf16[256*512]  [whi|wlo]
static const size_t O_WT2  = 72*MB;            // bf16[64*4096]  [whi|wlo]
static const size_t O_AGGB = 73*MB;            // bf16[20000*4096] hi|lo, 164MB
static const size_t O_SRC  = 73*MB;            // int[2E] temp (dead before AGGB)
static const size_t O_DST  = 79*MB;            // int[2E] temp
static const size_t O_H2P  = 238*MB;           // fp32[2 * N*64] (split-K halves)
static const size_t SCRATCH_BYTES = 250*MB;

__device__ __align__(1024) unsigned char g_scratch[SCRATCH_BYTES];

__device__ __forceinline__ float eluf(float x) { return x > 0.f ? x : expm1f(x); }
__device__ __forceinline__ float lrelu(float x) { return x > 0.f ? x : 0.2f * x; }

__device__ __forceinline__ void hl_split(float x, uint16_t& h, uint16_t& l) {
    __nv_bfloat16 hb = __float2bfloat16(x);
    h = __bfloat16_as_ushort(hb);
    l = __bfloat16_as_ushort(__float2bfloat16(x - __bfloat162float(hb)));
}

__device__ __forceinline__ void cpa16(uint32_t dst, const void* src, int szbytes) {
    asm volatile("cp.async.cg.shared.global [%0], [%1], 16, %2;"
                 :: "r"(dst), "l"(src), "r"(szbytes));
}

// ================= pipelined mma.sync bf16 GEMM =================
// C[rows x cols] = A[rows x 2K] (hi|lo) @ B[cols x 2K]^T (whi|wlo)
// HA = K/64. Iterations it in [0,2HA): it<HA: A_hi chunk vs {W_hi, W_lo};
// it>=HA: A_lo chunk vs W_hi. Split-K over blockIdx.z (z=0: [0,HA), z=1: [HA,2HA)).
template<int HA, int LDA, int LDB>
__global__ void __launch_bounds__(256) k_mmagemm(
    const uint16_t* __restrict__ A, const uint16_t* __restrict__ B,
    float* __restrict__ C, int nrows, int ldc, size_t zstride)
{
    extern __shared__ uint16_t sh[];
    uint16_t* Asm = sh;                 // [2][128*72]
    uint16_t* Bsm = sh + 2 * 9216;      // [2][2][64*72]
    int tid = threadIdx.x;
    int wm = tid >> 5, lane = tid & 31;
    int g = lane >> 2, t4 = lane & 3;
    int rowBase = blockIdx.x * 128;
    int colBase = blockIdx.y * 64;
    int itBeg, itEnd;
    if (gridDim.z == 1) { itBeg = 0; itEnd = 2 * HA; }
    else { itBeg = blockIdx.z * HA; itEnd = itBeg + HA; }
    C += (size_t)blockIdx.z * zstride;

    float c[8][4];
#pragma unroll
    for (int i = 0; i < 8; i++)
#pragma unroll
        for (int j = 0; j < 4; j++) c[i][j] = 0.f;

    uint32_t aBase = (uint32_t)__cvta_generic_to_shared(Asm);
    uint32_t bBase = (uint32_t)__cvta_generic_to_shared(Bsm);

    auto issue = [&](int it, int buf) {
        // A chunk: 128 rows x 64 halves
#pragma unroll
        for (int i = 0; i < 4; i++) {
            int s = i * 256 + tid;
            int row = s >> 3, k8 = s & 7;
            int gr = rowBase + row;
            const uint16_t* src = A + (size_t)gr * LDA + it * 64 + k8 * 8;
            cpa16(aBase + (buf * 9216 + row * 72 + k8 * 8) * 2, src, (gr < nrows) ? 16 : 0);
        }
        bool ph1 = it < HA;
        int b0 = ph1 ? it * 64 : (it - HA) * 64;
#pragma unroll
        for (int i = 0; i < 2; i++) {
            int s = i * 256 + tid;
            int row = s >> 3, k8 = s & 7;
            cpa16(bBase + (buf * 9216 + row * 72 + k8 * 8) * 2,
                  B + (size_t)(colBase + row) * LDB + b0 + k8 * 8, 16);
        }
        if (ph1) {
            int b1 = (HA + it) * 64;
#pragma unroll
            for (int i = 0; i < 2; i++) {
                int s = i * 256 + tid;
                int row = s >> 3, k8 = s & 7;
                cpa16(bBase + (buf * 9216 + 4608 + row * 72 + k8 * 8) * 2,
                      B + (size_t)(colBase + row) * LDB + b1 + k8 * 8, 16);
            }
        }
        asm volatile("cp.async.commit_group;" ::: "memory");
    };

    issue(itBeg, 0);
    for (int it = itBeg; it < itEnd; it++) {
        int buf = (it - itBeg) & 1;
        if (it + 1 < itEnd) {
            issue(it + 1, buf ^ 1);
            asm volatile("cp.async.wait_group 1;" ::: "memory");
        } else {
            asm volatile("cp.async.wait_group 0;" ::: "memory");
        }
        __syncthreads();
        bool ph1 = it < HA;
        const uint16_t* Ab = Asm + buf * 9216;
        const uint16_t* Bb = Bsm + buf * 9216;
#pragma unroll
        for (int ks = 0; ks < 4; ks++) {
            int k0 = ks * 16;
            uint32_t a0 = *(const uint32_t*)&Ab[(wm * 16 + g) * 72 + k0 + 2 * t4];
            uint32_t a1 = *(const uint32_t*)&Ab[(wm * 16 + g + 8) * 72 + k0 + 2 * t4];
            uint32_t a2 = *(const uint32_t*)&Ab[(wm * 16 + g) * 72 + k0 + 2 * t4 + 8];
            uint32_t a3 = *(const uint32_t*)&Ab[(wm * 16 + g + 8) * 72 + k0 + 2 * t4 + 8];
#pragma unroll
            for (int bt = 0; bt < 2; bt++) {
                if (bt == 1 && !ph1) break;
                const uint16_t* Bt = Bb + bt * 4608;
#pragma unroll
                for (int nf = 0; nf < 8; nf++) {
                    uint32_t b0 = *(const uint32_t*)&Bt[(nf * 8 + g) * 72 + k0 + 2 * t4];
                    uint32_t b1 = *(const uint32_t*)&Bt[(nf * 8 + g) * 72 + k0 + 2 * t4 + 8];
                    asm volatile(
                        "mma.sync.aligned.m16n8k16.row.col.f32.bf16.bf16.f32 "
                        "{%0,%1,%2,%3}, {%4,%5,%6,%7}, {%8,%9}, {%0,%1,%2,%3};"
                        : "+f"(c[nf][0]), "+f"(c[nf][1]), "+f"(c[nf][2]), "+f"(c[nf][3])
                        : "r"(a0), "r"(a1), "r"(a2), "r"(a3), "r"(b0), "r"(b1));
                }
            }
        }
        __syncthreads();
    }
    int r0 = rowBase + wm * 16 + g;
    int r1 = r0 + 8;
#pragma unroll
    for (int nf = 0; nf < 8; nf++) {
        int col = colBase + nf * 8 + 2 * t4;
        if (r0 < nrows) *(float2*)(C + (size_t)r0 * ldc + col) = make_float2(c[nf][0], c[nf][1]);
        if (r1 < nrows) *(float2*)(C + (size_t)r1 * ldc + col) = make_float2(c[nf][2], c[nf][3]);
    }
}

// ================= prep (also zeroes cnt) =================
__global__ void k_prep(const float* __restrict__ W2, const float* __restrict__ a2s,
                       const float* __restrict__ a2d, const float* __restrict__ b2,
                       const float* __restrict__ W1,
                       uint16_t* __restrict__ Wt1, uint16_t* __restrict__ Wt2,
                       float* __restrict__ ws, float* __restrict__ wd, float* __restrict__ bc,
                       int* __restrict__ cnt)
{
    int i = blockIdx.x * blockDim.x + threadIdx.x;
    if (i < 131072) {
        int n = i & 63, k = i >> 6;
        int t = k >> 10, r = k & 1023, h = r >> 7, cc = r & 127;
        float wv = W2[t * 65536 + cc * 512 + h * 64 + n] * 0.0625f;
        uint16_t hh, ll; hl_split(wv, hh, ll);
        uint16_t* p = Wt2 + (size_t)n * 4096 + k;
        p[0] = hh; p[2048] = ll;
    } else if (i < 196608) {
        int j = i - 131072;
        int np = j & 255, k = j >> 8;
        int t = np >> 7, n = np & 127;
        float wv = W1[t * 32768 + k * 128 + n];
        uint16_t hh, ll; hl_split(wv, hh, ll);
        uint16_t* p = Wt1 + (size_t)np * 512 + k;
        p[0] = hh; p[256] = ll;
    } else if (i < 198656) {
        int j = i - 196608;
        int t = j >> 10, r = j & 1023, h = r >> 7, cc = r & 127;
        const float* wrow = W2 + t * 65536 + cc * 512 + h * 64;
        const float* av = a2s + t * 512 + h * 64;
        float acc = 0.f;
        for (int o = 0; o < 64; o++) acc += wrow[o] * av[o];
        ws[j] = acc;
    } else if (i < 200704) {
        int j = i - 198656;
        int t = j >> 10, r = j & 1023, h = r >> 7, cc = r & 127;
        const float* wrow = W2 + t * 65536 + cc * 512 + h * 64;
        const float* av = a2d + t * 512 + h * 64;
        float acc = 0.f;
        for (int o = 0; o < 64; o++) acc += wrow[o] * av[o];
        wd[j] = acc;
    } else if (i < 200768) {
        int o = i - 200704;
        bc[o] = 0.5f * (b2[o] + b2[64 + o]);
    } else if (i < 240768) {
        cnt[i - 200768] = 0;
    }
}

// ================= graph preprocessing =================
__global__ void k_cvt(const void* pa, const void* pb, int* src, int* dst, int* cnt) {
    int t = blockIdx.y;
    const void* p = t ? pb : pa;
    unsigned ov = ((const unsigned*)p)[1 + 2 * (threadIdx.x & 31)];
    int is64 = __all_sync(0xffffffffu, ov == 0u);
    int i = blockIdx.x * blockDim.x + threadIdx.x;
    if (i >= E_) return;
    int s, d;
    if (is64) {
        const long long* q = (const long long*)p;
        s = (int)q[i]; d = (int)q[E_ + i];
    } else {
        const int* q = (const int*)p;
        s = q[i]; d = q[E_ + i];
    }
    src[t * E_ + i] = s;
    dst[t * E_ + i] = d;
    atomicAdd(&cnt[t * N_ + d], 1);
}

__global__ void k_cvtx(const float* __restrict__ x, uint16_t* __restrict__ xb) {
    int i = blockIdx.x * blockDim.x + threadIdx.x;
    if (i >= N_ * 64) return;
    int row = i >> 6, k4 = (i & 63) << 2;
    float4 v = ((const float4*)x)[i];
    uint16_t h0, l0, h1, l1, h2, l2, h3, l3;
    hl_split(v.x, h0, l0); hl_split(v.y, h1, l1);
    hl_split(v.z, h2, l2); hl_split(v.w, h3, l3);
    uint2 hi, lo;
    hi.x = (uint32_t)h0 | ((uint32_t)h1 << 16);
    hi.y = (uint32_t)h2 | ((uint32_t)h3 << 16);
    lo.x = (uint32_t)l0 | ((uint32_t)l1 << 16);
    lo.y = (uint32_t)l2 | ((uint32_t)l3 << 16);
    *(uint2*)(xb + (size_t)row * 512 + k4) = hi;
    *(uint2*)(xb + (size_t)row * 512 + 256 + k4) = lo;
}

__global__ void k_scan(const int* __restrict__ cnt, int* __restrict__ offs, int* __restrict__ cur)
{
    int t = blockIdx.x;
    const int4* c4 = (const int4*)(cnt + t * N_);
    int4* o4 = (int4*)(offs + t * N_);
    int4* q4 = (int4*)(cur + t * N_);
    __shared__ int wsum[32];
    __shared__ int sbase;
    int tid = threadIdx.x, lane = tid & 31, w = tid >> 5;
    if (tid == 0) sbase = 0;
    __syncthreads();
    const int N4 = N_ / 4;
    for (int i0 = 0; i0 < N4; i0 += 1024) {
        int i = i0 + tid;
        int4 c = make_int4(0, 0, 0, 0);
        if (i < N4) c = c4[i];
        int s = c.x + c.y + c.z + c.w;
        int x = s;
#pragma unroll
        for (int ofs = 1; ofs < 32; ofs <<= 1) {
            int y = __shfl_up_sync(0xffffffffu, x, ofs);
            if (lane >= ofs) x += y;
        }
        if (lane == 31) wsum[w] = x;
        __syncthreads();
        if (w == 0) {
            int v = wsum[lane];
#pragma unroll
            for (int ofs = 1; ofs < 32; ofs <<= 1) {
                int y = __shfl_up_sync(0xffffffffu, v, ofs);
                if (lane >= ofs) v += y;
            }
            wsum[lane] = v;
        }
        __syncthreads();
        int excl = sbase + (w ? wsum[w - 1] : 0) + x - s;
        if (i < N4) {
            int4 r;
            r.x = excl; r.y = excl + c.x; r.z = r.y + c.y; r.w = r.z + c.z;
            o4[i] = r; q4[i] = r;
        }
        __syncthreads();
        if (tid == 0) sbase += wsum[31];
        __syncthreads();
    }
}

__global__ void k_scatter(const int* __restrict__ src, const int* __restrict__ dst,
                          int* __restrict__ cur, int* __restrict__ csr)
{
    int i = blockIdx.x * blockDim.x + threadIdx.x;
    if (i >= 2 * E_) return;
    int t = (i >= E_) ? 1 : 0;
    int e = i - t * E_;
    int s = src[t * E_ + e], d = dst[t * E_ + e];
    int pos = atomicAdd(&cur[t * N_ + d], 1);
    csr[(size_t)t * E_ + pos] = s;
}

// ---------------- layer-1 scores ----------------
__global__ void k_scores1(const float* __restrict__ h1,
                          const float* __restrict__ a_src, const float* __restrict__ a_dst,
                          float* __restrict__ ss, float* __restrict__ sd)
{
    int node = blockIdx.x * 8 + (threadIdx.x >> 5);
    int lane = threadIdx.x & 31;
    int t = blockIdx.y;
    if (node >= N_) return;
    const float* hr = h1 + (size_t)node * 256 + t * 128;
    float4 v = *(const float4*)(hr + lane * 4);
    float4 w = *(const float4*)(a_src + t * 128 + lane * 4);
    float4 u = *(const float4*)(a_dst + t * 128 + lane * 4);
    float ps = v.x * w.x + v.y * w.y + v.z * w.z + v.w * w.w;
    float pd = v.x * u.x + v.y * u.y + v.z * u.z + v.w * u.w;
    ps += __shfl_xor_sync(0xffffffffu, ps, 1);
    ps += __shfl_xor_sync(0xffffffffu, ps, 2);
    pd += __shfl_xor_sync(0xffffffffu, pd, 1);
    pd += __shfl_xor_sync(0xffffffffu, pd, 2);
    if ((lane & 3) == 0) {
        ss[t * N_ * 8 + node * 8 + (lane >> 2)] = ps;
        sd[t * N_ * 8 + node * 8 + (lane >> 2)] = pd;
    }
}

// ---------------- layer-1 GAT: warp per (dst,type), fused scores2 ----------------
__global__ void __launch_bounds__(256) k_gat1(
    const int* __restrict__ offs, const int* __restrict__ cnt, const int* __restrict__ csr,
    const float* __restrict__ s1s, const float* __restrict__ s1d,
    const float* __restrict__ h1, const float* __restrict__ b1,
    float* __restrict__ h1c,
    const float* __restrict__ ws, const float* __restrict__ wd,
    float* __restrict__ s2s, float* __restrict__ s2d)
{
    __shared__ float sa[8][256];
    __shared__ float4 accs[8][32];
    int w = threadIdx.x >> 5, lane = threadIdx.x & 31;
    int d = blockIdx.x * 4 + (w >> 1);
    int t = w & 1;
    int hd = lane >> 2;
    float4 acc = make_float4(0.f, 0.f, 0.f, 0.f);
    if (d < N_) {
        int beg = offs[t * N_ + d], n = cnt[t * N_ + d];
        const float* ss = s1s + (size_t)t * N_ * 8;
        const float4* sdp = (const float4*)(s1d + ((size_t)t * N_ + d) * 8);
        float4 sd0 = sdp[0], sd1 = sdp[1];
        float sdv[8] = {sd0.x, sd0.y, sd0.z, sd0.w, sd1.x, sd1.y, sd1.z, sd1.w};
        const int* cs = csr + (size_t)t * E_ + beg;
        float zp[8];
#pragma unroll
        for (int k = 0; k < 8; k++) zp[k] = 0.f;
        for (int c0 = 0; c0 < n; c0 += 32) {
            int m = n - c0; if (m > 32) m = 32;
            if (lane < m) {
                int sL = cs[c0 + lane];
                float4 a0 = *(const float4*)(ss + (size_t)sL * 8);
                float4 a1 = *(const float4*)(ss + (size_t)sL * 8 + 4);
                zp[0] += __expf(lrelu(a0.x + sdv[0]));
                zp[1] += __expf(lrelu(a0.y + sdv[1]));
                zp[2] += __expf(lrelu(a0.z + sdv[2]));
                zp[3] += __expf(lrelu(a0.w + sdv[3]));
                zp[4] += __expf(lrelu(a1.x + sdv[4]));
                zp[5] += __expf(lrelu(a1.y + sdv[5]));
                zp[6] += __expf(lrelu(a1.z + sdv[6]));
                zp[7] += __expf(lrelu(a1.w + sdv[7]));
            }
        }
        float izv[8];
#pragma unroll
        for (int k = 0; k < 8; k++) {
            float v = zp[k];
            v += __shfl_xor_sync(0xffffffffu, v, 1);
            v += __shfl_xor_sync(0xffffffffu, v, 2);
            v += __shfl_xor_sync(0xffffffffu, v, 4);
            v += __shfl_xor_sync(0xffffffffu, v, 8);
            v += __shfl_xor_sync(0xffffffffu, v, 16);
            izv[k] = 1.f / v;
        }
        for (int c0 = 0; c0 < n; c0 += 32) {
            int m = n - c0; if (m > 32) m = 32;
            int sL = 0;
            if (lane < m) {
                sL = cs[c0 + lane];
                float4 a0 = *(const float4*)(ss + (size_t)sL * 8);
                float4 a1 = *(const float4*)(ss + (size_t)sL * 8 + 4);
                float4 e0, e1;
                e0.x = __expf(lrelu(a0.x + sdv[0])) * izv[0];
                e0.y = __expf(lrelu(a0.y + sdv[1])) * izv[1];
                e0.z = __expf(lrelu(a0.z + sdv[2])) * izv[2];
                e0.w = __expf(lrelu(a0.w + sdv[3])) * izv[3];
                e1.x = __expf(lrelu(a1.x + sdv[4])) * izv[4];
                e1.y = __expf(lrelu(a1.y + sdv[5])) * izv[5];
                e1.z = __expf(lrelu(a1.z + sdv[6])) * izv[6];
                e1.w = __expf(lrelu(a1.w + sdv[7])) * izv[7];
                *(float4*)&sa[w][lane * 8] = e0;
                *(float4*)&sa[w][lane * 8 + 4] = e1;
            }
            __syncwarp();
#pragma unroll
            for (int j = 0; j < 32; j++) {
                if (j < m) {
                    int sj = __shfl_sync(0xffffffffu, sL, j);
                    float a = sa[w][j * 8 + hd];
                    float4 v = *(const float4*)(h1 + (size_t)sj * 256 + t * 128 + lane * 4);
                    acc.x = fmaf(a, v.x, acc.x);
                    acc.y = fmaf(a, v.y, acc.y);
                    acc.z = fmaf(a, v.z, acc.z);
                    acc.w = fmaf(a, v.w, acc.w);
                }
            }
            __syncwarp();
        }
    }
    accs[w][lane] = acc;
    __syncthreads();
    if (t == 0 && d < N_) {
        float4 a0 = accs[w][lane], a1 = accs[w + 1][lane];
        float4 bb0 = *(const float4*)(b1 + lane * 4);
        float4 bb1 = *(const float4*)(b1 + 128 + lane * 4);
        float4 r;
        r.x = eluf(0.5f * (a0.x + a1.x + bb0.x + bb1.x));
        r.y = eluf(0.5f * (a0.y + a1.y + bb0.y + bb1.y));
        r.z = eluf(0.5f * (a0.z + a1.z + bb0.z + bb1.z));
        r.w = eluf(0.5f * (a0.w + a1.w + bb0.w + bb1.w));
        *(float4*)(h1c + (size_t)d * 128 + lane * 4) = r;
        // fused layer-2 scores
#pragma unroll
        for (int c = 0; c < 16; c++) {
            float4 wv = *(const float4*)(ws + c * 128 + lane * 4);
            float p = r.x * wv.x + r.y * wv.y + r.z * wv.z + r.w * wv.w;
            p += __shfl_xor_sync(0xffffffffu, p, 16);
            p += __shfl_xor_sync(0xffffffffu, p, 8);
            p += __shfl_xor_sync(0xffffffffu, p, 4);
            p += __shfl_xor_sync(0xffffffffu, p, 2);
            p += __shfl_xor_sync(0xffffffffu, p, 1);
            float4 uv = *(const float4*)(wd + c * 128 + lane * 4);
            float q = r.x * uv.x + r.y * uv.y + r.z * uv.z + r.w * uv.w;
            q += __shfl_xor_sync(0xffffffffu, q, 16);
            q += __shfl_xor_sync(0xffffffffu, q, 8);
            q += __shfl_xor_sync(0xffffffffu, q, 4);
            q += __shfl_xor_sync(0xffffffffu, q, 2);
            q += __shfl_xor_sync(0xffffffffu, q, 1);
            if (lane == 0) {
                s2s[(c >> 3) * N_ * 8 + d * 8 + (c & 7)] = p;
                s2d[(c >> 3) * N_ * 8 + d * 8 + (c & 7)] = q;
            }
        }
    }
}

// ---------------- layer-2 aggregate: warp per (dst,type) -> bf16 hi|lo ----------------
__global__ void __launch_bounds__(256) k_gat2(
    const int* __restrict__ offs, const int* __restrict__ cnt, const int* __restrict__ csr,
    const float* __restrict__ s2s, const float* __restrict__ s2d,
    const float* __restrict__ h1c, uint16_t* __restrict__ aggb)
{
    __shared__ float sa[8][256];
    int w = threadIdx.x >> 5, lane = threadIdx.x & 31;
    int d = blockIdx.x * 4 + (w >> 1);
    int t = w & 1;
    if (d >= N_) return;
    int beg = offs[t * N_ + d], n = cnt[t * N_ + d];
    const float* ss = s2s + (size_t)t * N_ * 8;
    const float4* sdp = (const float4*)(s2d + ((size_t)t * N_ + d) * 8);
    float4 sd0 = sdp[0], sd1 = sdp[1];
    float sdv[8] = {sd0.x, sd0.y, sd0.z, sd0.w, sd1.x, sd1.y, sd1.z, sd1.w};
    const int* cs = csr + (size_t)t * E_ + beg;
    float zp[8];
#pragma unroll
    for (int k = 0; k < 8; k++) zp[k] = 0.f;
    for (int c0 = 0; c0 < n; c0 += 32) {
        int m = n - c0; if (m > 32) m = 32;
        if (lane < m) {
            int sL = cs[c0 + lane];
            float4 a0 = *(const float4*)(ss + (size_t)sL * 8);
            float4 a1 = *(const float4*)(ss + (size_t)sL * 8 + 4);
            zp[0] += __expf(lrelu(a0.x + sdv[0]));
            zp[1] += __expf(lrelu(a0.y + sdv[1]));
            zp[2] += __expf(lrelu(a0.z + sdv[2]));
            zp[3] += __expf(lrelu(a0.w + sdv[3]));
            zp[4] += __expf(lrelu(a1.x + sdv[4]));
            zp[5] += __expf(lrelu(a1.y + sdv[5]));
            zp[6] += __expf(lrelu(a1.z + sdv[6]));
            zp[7] += __expf(lrelu(a1.w + sdv[7]));
        }
    }
    float izv[8];
#pragma unroll
    for (int k = 0; k < 8; k++) {
        float v = zp[k];
        v += __shfl_xor_sync(0xffffffffu, v, 1);
        v += __shfl_xor_sync(0xffffffffu, v, 2);
        v += __shfl_xor_sync(0xffffffffu, v, 4);
        v += __shfl_xor_sync(0xffffffffu, v, 8);
        v += __shfl_xor_sync(0xffffffffu, v, 16);
        izv[k] = 1.f / v;
    }
    float4 acc[8];
#pragma unroll
    for (int h = 0; h < 8; h++) acc[h] = make_float4(0.f, 0.f, 0.f, 0.f);
    for (int c0 = 0; c0 < n; c0 += 32) {
        int m = n - c0; if (m > 32) m = 32;
        int sL = 0;
        if (lane < m) {
            sL = cs[c0 + lane];
            float4 a0 = *(const float4*)(ss + (size_t)sL * 8);
            float4 a1 = *(const float4*)(ss + (size_t)sL * 8 + 4);
            float4 e0, e1;
            e0.x = __expf(lrelu(a0.x + sdv[0])) * izv[0];
            e0.y = __expf(lrelu(a0.y + sdv[1])) * izv[1];
            e0.z = __expf(lrelu(a0.z + sdv[2])) * izv[2];
            e0.w = __expf(lrelu(a0.w + sdv[3])) * izv[3];
            e1.x = __expf(lrelu(a1.x + sdv[4])) * izv[4];
            e1.y = __expf(lrelu(a1.y + sdv[5])) * izv[5];
            e1.z = __expf(lrelu(a1.z + sdv[6])) * izv[6];
            e1.w = __expf(lrelu(a1.w + sdv[7])) * izv[7];
            *(float4*)&sa[w][lane * 8] = e0;
            *(float4*)&sa[w][lane * 8 + 4] = e1;
        }
        __syncwarp();
#pragma unroll
        for (int j = 0; j < 32; j++) {
            if (j < m) {
                int sj = __shfl_sync(0xffffffffu, sL, j);
                float4 a0 = *(const float4*)&sa[w][j * 8];
                float4 a1 = *(const float4*)&sa[w][j * 8 + 4];
                float4 v = *(const float4*)(h1c + (size_t)sj * 128 + lane * 4);
                acc[0].x = fmaf(a0.x, v.x, acc[0].x); acc[0].y = fmaf(a0.x, v.y, acc[0].y);
                acc[0].z = fmaf(a0.x, v.z, acc[0].z); acc[0].w = fmaf(a0.x, v.w, acc[0].w);
                acc[1].x = fmaf(a0.y, v.x, acc[1].x); acc[1].y = fmaf(a0.y, v.y, acc[1].y);
                acc[1].z = fmaf(a0.y, v.z, acc[1].z); acc[1].w = fmaf(a0.y, v.w, acc[1].w);
                acc[2].x = fmaf(a0.z, v.x, acc[2].x); acc[2].y = fmaf(a0.z, v.y, acc[2].y);
                acc[2].z = fmaf(a0.z, v.z, acc[2].z); acc[2].w = fmaf(a0.z, v.w, acc[2].w);
                acc[3].x = fmaf(a0.w, v.x, acc[3].x); acc[3].y = fmaf(a0.w, v.y, acc[3].y);
                acc[3].z = fmaf(a0.w, v.z, acc[3].z); acc[3].w = fmaf(a0.w, v.w, acc[3].w);
                acc[4].x = fmaf(a1.x, v.x, acc[4].x); acc[4].y = fmaf(a1.x, v.y, acc[4].y);
                acc[4].z = fmaf(a1.x, v.z, acc[4].z); acc[4].w = fmaf(a1.x, v.w, acc[4].w);
                acc[5].x = fmaf(a1.y, v.x, acc[5].x); acc[5].y = fmaf(a1.y, v.y, acc[5].y);
                acc[5].z = fmaf(a1.y, v.z, acc[5].z); acc[5].w = fmaf(a1.y, v.w, acc[5].w);
                acc[6].x = fmaf(a1.z, v.x, acc[6].x); acc[6].y = fmaf(a1.z, v.y, acc[6].y);
                acc[6].z = fmaf(a1.z, v.z, acc[6].z); acc[6].w = fmaf(a1.z, v.w, acc[6].w);
                acc[7].x = fmaf(a1.w, v.x, acc[7].x); acc[7].y = fmaf(a1.w, v.y, acc[7].y);
                acc[7].z = fmaf(a1.w, v.z, acc[7].z); acc[7].w = fmaf(a1.w, v.w, acc[7].w);
            }
        }
        __syncwarp();
    }
#pragma unroll
    for (int h = 0; h < 8; h++) {
        uint16_t h0, l0, h1v, l1, h2, l2, h3, l3;
        hl_split(acc[h].x, h0, l0); hl_split(acc[h].y, h1v, l1);
        hl_split(acc[h].z, h2, l2); hl_split(acc[h].w, h3, l3);
        uint2 hi, lo;
        hi.x = (uint32_t)h0 | ((uint32_t)h1v << 16);
        hi.y = (uint32_t)h2 | ((uint32_t)h3 << 16);
        lo.x = (uint32_t)l0 | ((uint32_t)l1 << 16);
        lo.y = (uint32_t)l2 | ((uint32_t)l3 << 16);
        int k = t * 1024 + h * 128 + lane * 4;
        *(uint2*)(aggb + (size_t)d * 4096 + k) = hi;
        *(uint2*)(aggb + (size_t)d * 4096 + 2048 + k) = lo;
    }
}

// ---------------- classifier (sums split-K halves, bias + ELU fused) ----------------
__global__ void k_classifier(const float* __restrict__ h, const float* __restrict__ bc,
                             const float* __restrict__ Wc1, const float* __restrict__ bc1,
                             const float* __restrict__ Wc2, const float* __restrict__ bc2,
                             float* __restrict__ out)
{
    int wid = (blockIdx.x * blockDim.x + threadIdx.x) >> 5;
    int lane = threadIdx.x & 31;
    if (wid >= N_) return;
    const float* hr = h + (size_t)wid * 64;
    const float* hr2 = hr + (size_t)N_ * 64;
    float acc = bc1[lane];
#pragma unroll
    for (int c = 0; c < 64; c++) {
        float hv = eluf(__ldg(hr + c) + __ldg(hr2 + c) + __ldg(bc + c));
        acc = fmaf(hv, Wc1[c * 32 + lane], acc);
    }
    acc = fmaxf(acc, 0.f);
    float p0 = acc * Wc2[lane * 2];
    float p1 = acc * Wc2[lane * 2 + 1];
#pragma unroll
    for (int o = 16; o >= 1; o >>= 1) {
        p0 += __shfl_xor_sync(0xffffffffu, p0, o);
        p1 += __shfl_xor_sync(0xffffffffu, p1, o);
    }
    if (lane == 0) {
        out[wid * 2 + 0] = p0 + bc2[0];
        out[wid * 2 + 1] = p1 + bc2[1];
    }
}

// ---------------- launch ----------------
extern "C" void kernel_launch(void* const* d_in, const int* in_sizes, int n_in,
                              void* d_out, int out_size)
{
    const float* x    = (const float*)d_in[0];
    const void*  eia  = d_in[1];
    const void*  eib  = d_in[2];
    const float* W1   = (const float*)d_in[3];
    const float* a1s  = (const float*)d_in[4];
    const float* a1d  = (const float*)d_in[5];
    const float* b1   = (const float*)d_in[6];
    const float* W2   = (const float*)d_in[7];
    const float* a2s  = (const float*)d_in[8];
    const float* a2d  = (const float*)d_in[9];
    const float* b2   = (const float*)d_in[10];
    const float* Wc1  = (const float*)d_in[11];
    const float* bc1  = (const float*)d_in[12];
    const float* Wc2  = (const float*)d_in[13];
    const float* bc2  = (const float*)d_in[14];
    float* out = (float*)d_out;

    void* basev = nullptr;
    cudaGetSymbolAddress(&basev, g_scratch);
    unsigned char* base = (unsigned char*)basev;

    int*      p_csr  = (int*)(base + O_CSR);
    int*      p_cnt  = (int*)(base + O_CNT);
    int*      p_off  = (int*)(base + O_OFF);
    int*      p_cur  = (int*)(base + O_CUR);
    uint16_t* p_xb   = (uint16_t*)(base + O_XB);
    float*    p_h1   = (float*)(base + O_H1);
    float*    p_s1s  = (float*)(base + O_S1S);
    float*    p_s1d  = (float*)(base + O_S1D);
    float*    p_h1c  = (float*)(base + O_H1C);
    float*    p_s2s  = (float*)(base + O_S2S);
    float*    p_s2d  = (float*)(base + O_S2D);
    float*    p_ws   = (float*)(base + O_WS);
    float*    p_wd   = (float*)(base + O_WD);
    float*    p_bc   = (float*)(base + O_BC);
    uint16_t* p_wt1  = (uint16_t*)(base + O_WT1);
    uint16_t* p_wt2  = (uint16_t*)(base + O_WT2);
    uint16_t* p_aggb = (uint16_t*)(base + O_AGGB);
    int*      p_src  = (int*)(base + O_SRC);
    int*      p_dst  = (int*)(base + O_DST);
    float*    p_h2p  = (float*)(base + O_H2P);

    cudaFuncSetAttribute(k_mmagemm<4, 512, 512>,
                         cudaFuncAttributeMaxDynamicSharedMemorySize, 73728);
    cudaFuncSetAttribute(k_mmagemm<32, 4096, 4096>,
                         cudaFuncAttributeMaxDynamicSharedMemorySize, 73728);

    // 1-3: prep (zeros cnt), cvt (+histogram), cvtx
    k_prep<<<(240768 + 255) / 256, 256>>>(W2, a2s, a2d, b2, W1, p_wt1, p_wt2,
                                          p_ws, p_wd, p_bc, p_cnt);
    k_cvt<<<dim3((E_ + 255) / 256, 2), 256>>>(eia, eib, p_src, p_dst, p_cnt);
    k_cvtx<<<(N_ * 64 + 255) / 256, 256>>>(x, p_xb);

    // 4: layer-1 GEMM (profiled by ncu)
    k_mmagemm<4, 512, 512><<<dim3(157, 4, 1), 256, 73728>>>(p_xb, p_wt1, p_h1, N_, 256, 0);

    // 5-6: finish CSR
    k_scan<<<2, 1024>>>(p_cnt, p_off, p_cur);
    k_scatter<<<(2 * E_ + 255) / 256, 256>>>(p_src, p_dst, p_cur, p_csr);

    // 7-9: scores -> gat1 (writes h1c + layer-2 scores) -> gat2
    k_scores1<<<dim3((N_ + 7) / 8, 2), 256>>>(p_h1, a1s, a1d, p_s1s, p_s1d);
    k_gat1<<<(N_ + 3) / 4, 256>>>(p_off, p_cnt, p_csr, p_s1s, p_s1d, p_h1, b1,
                                  p_h1c, p_ws, p_wd, p_s2s, p_s2d);
    k_gat2<<<(N_ + 3) / 4, 256>>>(p_off, p_cnt, p_csr, p_s2s, p_s2d, p_h1c, p_aggb);

    // 10: layer-2 GEMM, split-K=2
    k_mmagemm<32, 4096, 4096><<<dim3(157, 1, 2), 256, 73728>>>(
        p_aggb, p_wt2, p_h2p, N_, 64, (size_t)N_ * 64);

    // 11: classifier
    k_classifier<<<(N_ * 32 + 255) / 256, 256>>>(p_h2p, p_bc, Wc1, bc1, Wc2, bc2, out);
}

// round 8
// speedup vs baseline: 1.6013x; 1.1108x over previous
#include <cuda_runtime.h>
#include <cuda_bf16.h>
#include <cstdint>
#include <cstddef>

#define N_ 20000
#define E_ 640000
#define MB (1048576ull)

// ---------------- scratch layout ----------------
static const size_t O_CSR  = 0;                // int[2E] 5.12MB
static const size_t O_CNT  = 6*MB;
static const size_t O_OFF  = 7*MB;
static const size_t O_CUR  = 8*MB;
static const size_t O_XB   = 9*MB;             // bf16[20000*512] hi|lo, 20.5MB
static const size_t O_H1   = 30*MB;            // fp32[20000*256] 20.5MB
static const size_t O_S1S  = 51*MB;            // fp32[2*N*8]
static const size_t O_S1D  = 53*MB;
static const size_t O_H1C  = 55*MB;            // fp32[N*128] 10.2MB
static const size_t O_S2S  = 66*MB;
static const size_t O_S2D  = 68*MB;
static const size_t O_WS   = 70*MB;            // fp32[2048]
static const size_t O_WD   = 70*MB + 16384;
static const size_t O_BC   = 70*MB + 32768;
static const size_t O_WT1  = 71*MB;            // bf16[256*512]  [whi|wlo]
static const size_t O_WT2  = 72*MB;            // bf16[64*4096]  [whi|wlo]
static const size_t O_AGGB = 73*MB;            // bf16[20000*4096] hi|lo, 164MB
static const size_t O_SRC  = 73*MB;            // int[2E] temp (dead before AGGB)
static const size_t O_DST  = 79*MB;            // int[2E] temp
static const size_t O_H2P  = 238*MB;           // fp32[4 * N*64] (split-K parts) 20.5MB
static const size_t SCRATCH_BYTES = 262*MB;

__device__ __align__(1024) unsigned char g_scratch[SCRATCH_BYTES];

__device__ __forceinline__ float eluf(float x) { return x > 0.f ? x : expm1f(x); }
__device__ __forceinline__ float lrelu(float x) { return x > 0.f ? x : 0.2f * x; }

__device__ __forceinline__ void hl_split(float x, uint16_t& h, uint16_t& l) {
    __nv_bfloat16 hb = __float2bfloat16(x);
    h = __bfloat16_as_ushort(hb);
    l = __bfloat16_as_ushort(__float2bfloat16(x - __bfloat162float(hb)));
}

__device__ __forceinline__ void cpa16(uint32_t dst, const void* src, int szbytes) {
    asm volatile("cp.async.cg.shared.global [%0], [%1], 16, %2;"
                 :: "r"(dst), "l"(src), "r"(szbytes));
}

__device__ __forceinline__ void ldsm4(uint32_t* r, uint32_t addr) {
    asm volatile("ldmatrix.sync.aligned.m8n8.x4.shared.b16 {%0,%1,%2,%3}, [%4];"
                 : "=r"(r[0]), "=r"(r[1]), "=r"(r[2]), "=r"(r[3]) : "r"(addr));
}

// ================= pipelined mma.sync bf16 GEMM (ldmatrix fragments) =================
// C[rows x cols] = A[rows x 2K] (hi|lo) @ B[cols x 2K]^T (whi|wlo)
// HA = K/64. it<HA: A_hi vs {W_hi, W_lo}; it>=HA: A_lo vs W_hi.
// Split-K over blockIdx.z: each z does span = 2HA/Z consecutive iterations.
template<int HA, int LDA, int LDB>
__global__ void __launch_bounds__(256) k_mmagemm(
    const uint16_t* __restrict__ A, const uint16_t* __restrict__ B,
    float* __restrict__ C, int nrows, int ldc, size_t zstride)
{
    extern __shared__ uint16_t sh[];
    uint16_t* Asm = sh;                 // [2][128*72]
    uint16_t* Bsm = sh + 2 * 9216;      // [2][2][64*72]
    int tid = threadIdx.x;
    int wm = tid >> 5, lane = tid & 31;
    int g = lane >> 2, t4 = lane & 3;
    int rowBase = blockIdx.x * 128;
    int colBase = blockIdx.y * 64;
    int span = (2 * HA) / gridDim.z;
    int itBeg = blockIdx.z * span, itEnd = itBeg + span;
    C += (size_t)blockIdx.z * zstride;

    float c[8][4];
#pragma unroll
    for (int i = 0; i < 8; i++)
#pragma unroll
        for (int j = 0; j < 4; j++) c[i][j] = 0.f;

    uint32_t aBase = (uint32_t)__cvta_generic_to_shared(Asm);
    uint32_t bBase = (uint32_t)__cvta_generic_to_shared(Bsm);

    auto issue = [&](int it, int buf) {
#pragma unroll
        for (int i = 0; i < 4; i++) {
            int s = i * 256 + tid;
            int row = s >> 3, k8 = s & 7;
            int gr = rowBase + row;
            const uint16_t* src = A + (size_t)gr * LDA + it * 64 + k8 * 8;
            cpa16(aBase + (buf * 9216 + row * 72 + k8 * 8) * 2, src, (gr < nrows) ? 16 : 0);
        }
        bool ph1 = it < HA;
        int b0 = ph1 ? it * 64 : (it - HA) * 64;
#pragma unroll
        for (int i = 0; i < 2; i++) {
            int s = i * 256 + tid;
            int row = s >> 3, k8 = s & 7;
            cpa16(bBase + (buf * 9216 + row * 72 + k8 * 8) * 2,
                  B + (size_t)(colBase + row) * LDB + b0 + k8 * 8, 16);
        }
        if (ph1) {
            int b1 = (HA + it) * 64;
#pragma unroll
            for (int i = 0; i < 2; i++) {
                int s = i * 256 + tid;
                int row = s >> 3, k8 = s & 7;
                cpa16(bBase + (buf * 9216 + 4608 + row * 72 + k8 * 8) * 2,
                      B + (size_t)(colBase + row) * LDB + b1 + k8 * 8, 16);
            }
        }
        asm volatile("cp.async.commit_group;" ::: "memory");
    };

    issue(itBeg, 0);
    for (int it = itBeg; it < itEnd; it++) {
        int buf = (it - itBeg) & 1;
        if (it + 1 < itEnd) {
            issue(it + 1, buf ^ 1);
            asm volatile("cp.async.wait_group 1;" ::: "memory");
        } else {
            asm volatile("cp.async.wait_group 0;" ::: "memory");
        }
        __syncthreads();
        bool ph1 = it < HA;
#pragma unroll
        for (int ks = 0; ks < 4; ks++) {
            int k0 = ks * 16;
            // A fragments: one ldmatrix.x4
            uint32_t ar[4];
            {
                int row = wm * 16 + (lane & 15);
                int col = k0 + 8 * (lane >> 4);
                ldsm4(ar, aBase + (buf * 9216 + row * 72 + col) * 2);
            }
#pragma unroll
            for (int bt = 0; bt < 2; bt++) {
                if (bt == 1 && !ph1) break;
                uint32_t br[16];
#pragma unroll
                for (int j = 0; j < 4; j++) {
                    int n = j * 16 + 8 * (lane >> 4) + (lane & 7);
                    int col = k0 + 8 * ((lane >> 3) & 1);
                    ldsm4(br + 4 * j, bBase + (buf * 9216 + bt * 4608 + n * 72 + col) * 2);
                }
#pragma unroll
                for (int nf = 0; nf < 8; nf++) {
                    uint32_t b0 = br[4 * (nf >> 1) + 2 * (nf & 1)];
                    uint32_t b1 = br[4 * (nf >> 1) + 2 * (nf & 1) + 1];
                    asm volatile(
                        "mma.sync.aligned.m16n8k16.row.col.f32.bf16.bf16.f32 "
                        "{%0,%1,%2,%3}, {%4,%5,%6,%7}, {%8,%9}, {%0,%1,%2,%3};"
                        : "+f"(c[nf][0]), "+f"(c[nf][1]), "+f"(c[nf][2]), "+f"(c[nf][3])
                        : "r"(ar[0]), "r"(ar[1]), "r"(ar[2]), "r"(ar[3]), "r"(b0), "r"(b1));
                }
            }
        }
        __syncthreads();
    }
    int r0 = rowBase + wm * 16 + g;
    int r1 = r0 + 8;
#pragma unroll
    for (int nf = 0; nf < 8; nf++) {
        int col = colBase + nf * 8 + 2 * t4;
        if (r0 < nrows) *(float2*)(C + (size_t)r0 * ldc + col) = make_float2(c[nf][0], c[nf][1]);
        if (r1 < nrows) *(float2*)(C + (size_t)r1 * ldc + col) = make_float2(c[nf][2], c[nf][3]);
    }
}

// ================= prep (also zeroes cnt) =================
__global__ void k_prep(const float* __restrict__ W2, const float* __restrict__ a2s,
                       const float* __restrict__ a2d, const float* __restrict__ b2,
                       const float* __restrict__ W1,
                       uint16_t* __restrict__ Wt1, uint16_t* __restrict__ Wt2,
                       float* __restrict__ ws, float* __restrict__ wd, float* __restrict__ bc,
                       int* __restrict__ cnt)
{
    int i = blockIdx.x * blockDim.x + threadIdx.x;
    if (i < 131072) {
        int n = i & 63, k = i >> 6;
        int t = k >> 10, r = k & 1023, h = r >> 7, cc = r & 127;
        float wv = W2[t * 65536 + cc * 512 + h * 64 + n] * 0.0625f;
        uint16_t hh, ll; hl_split(wv, hh, ll);
        uint16_t* p = Wt2 + (size_t)n * 4096 + k;
        p[0] = hh; p[2048] = ll;
    } else if (i < 196608) {
        int j = i - 131072;
        int np = j & 255, k = j >> 8;
        int t = np >> 7, n = np & 127;
        float wv = W1[t * 32768 + k * 128 + n];
        uint16_t hh, ll; hl_split(wv, hh, ll);
        uint16_t* p = Wt1 + (size_t)np * 512 + k;
        p[0] = hh; p[256] = ll;
    } else if (i < 198656) {
        int j = i - 196608;
        int t = j >> 10, r = j & 1023, h = r >> 7, cc = r & 127;
        const float* wrow = W2 + t * 65536 + cc * 512 + h * 64;
        const float* av = a2s + t * 512 + h * 64;
        float acc = 0.f;
        for (int o = 0; o < 64; o++) acc += wrow[o] * av[o];
        ws[j] = acc;
    } else if (i < 200704) {
        int j = i - 198656;
        int t = j >> 10, r = j & 1023, h = r >> 7, cc = r & 127;
        const float* wrow = W2 + t * 65536 + cc * 512 + h * 64;
        const float* av = a2d + t * 512 + h * 64;
        float acc = 0.f;
        for (int o = 0; o < 64; o++) acc += wrow[o] * av[o];
        wd[j] = acc;
    } else if (i < 200768) {
        int o = i - 200704;
        bc[o] = 0.5f * (b2[o] + b2[64 + o]);
    } else if (i < 240768) {
        cnt[i - 200768] = 0;
    }
}

// ================= graph preprocessing =================
__global__ void k_cvt(const void* pa, const void* pb, int* src, int* dst, int* cnt) {
    int t = blockIdx.y;
    const void* p = t ? pb : pa;
    unsigned ov = ((const unsigned*)p)[1 + 2 * (threadIdx.x & 31)];
    int is64 = __all_sync(0xffffffffu, ov == 0u);
    int i = blockIdx.x * blockDim.x + threadIdx.x;
    if (i >= E_) return;
    int s, d;
    if (is64) {
        const long long* q = (const long long*)p;
        s = (int)q[i]; d = (int)q[E_ + i];
    } else {
        const int* q = (const int*)p;
        s = q[i]; d = q[E_ + i];
    }
    src[t * E_ + i] = s;
    dst[t * E_ + i] = d;
    atomicAdd(&cnt[t * N_ + d], 1);
}

__global__ void k_cvtx(const float* __restrict__ x, uint16_t* __restrict__ xb) {
    int i = blockIdx.x * blockDim.x + threadIdx.x;
    if (i >= N_ * 64) return;
    int row = i >> 6, k4 = (i & 63) << 2;
    float4 v = ((const float4*)x)[i];
    uint16_t h0, l0, h1, l1, h2, l2, h3, l3;
    hl_split(v.x, h0, l0); hl_split(v.y, h1, l1);
    hl_split(v.z, h2, l2); hl_split(v.w, h3, l3);
    uint2 hi, lo;
    hi.x = (uint32_t)h0 | ((uint32_t)h1 << 16);
    hi.y = (uint32_t)h2 | ((uint32_t)h3 << 16);
    lo.x = (uint32_t)l0 | ((uint32_t)l1 << 16);
    lo.y = (uint32_t)l2 | ((uint32_t)l3 << 16);
    *(uint2*)(xb + (size_t)row * 512 + k4) = hi;
    *(uint2*)(xb + (size_t)row * 512 + 256 + k4) = lo;
}

__global__ void k_scan(const int* __restrict__ cnt, int* __restrict__ offs, int* __restrict__ cur)
{
    int t = blockIdx.x;
    const int4* c4 = (const int4*)(cnt + t * N_);
    int4* o4 = (int4*)(offs + t * N_);
    int4* q4 = (int4*)(cur + t * N_);
    __shared__ int wsum[32];
    __shared__ int sbase;
    int tid = threadIdx.x, lane = tid & 31, w = tid >> 5;
    if (tid == 0) sbase = 0;
    __syncthreads();
    const int N4 = N_ / 4;
    for (int i0 = 0; i0 < N4; i0 += 1024) {
        int i = i0 + tid;
        int4 c = make_int4(0, 0, 0, 0);
        if (i < N4) c = c4[i];
        int s = c.x + c.y + c.z + c.w;
        int x = s;
#pragma unroll
        for (int ofs = 1; ofs < 32; ofs <<= 1) {
            int y = __shfl_up_sync(0xffffffffu, x, ofs);
            if (lane >= ofs) x += y;
        }
        if (lane == 31) wsum[w] = x;
        __syncthreads();
        if (w == 0) {
            int v = wsum[lane];
#pragma unroll
            for (int ofs = 1; ofs < 32; ofs <<= 1) {
                int y = __shfl_up_sync(0xffffffffu, v, ofs);
                if (lane >= ofs) v += y;
            }
            wsum[lane] = v;
        }
        __syncthreads();
        int excl = sbase + (w ? wsum[w - 1] : 0) + x - s;
        if (i < N4) {
            int4 r;
            r.x = excl; r.y = excl + c.x; r.z = r.y + c.y; r.w = r.z + c.z;
            o4[i] = r; q4[i] = r;
        }
        __syncthreads();
        if (tid == 0) sbase += wsum[31];
        __syncthreads();
    }
}

__global__ void k_scatter(const int* __restrict__ src, const int* __restrict__ dst,
                          int* __restrict__ cur, int* __restrict__ csr)
{
    int i = blockIdx.x * blockDim.x + threadIdx.x;
    if (i >= 2 * E_) return;
    int t = (i >= E_) ? 1 : 0;
    int e = i - t * E_;
    int s = src[t * E_ + e], d = dst[t * E_ + e];
    int pos = atomicAdd(&cur[t * N_ + d], 1);
    csr[(size_t)t * E_ + pos] = s;
}

// ---------------- layer-1 scores ----------------
__global__ void k_scores1(const float* __restrict__ h1,
                          const float* __restrict__ a_src, const float* __restrict__ a_dst,
                          float* __restrict__ ss, float* __restrict__ sd)
{
    int node = blockIdx.x * 8 + (threadIdx.x >> 5);
    int lane = threadIdx.x & 31;
    int t = blockIdx.y;
    if (node >= N_) return;
    const float* hr = h1 + (size_t)node * 256 + t * 128;
    float4 v = *(const float4*)(hr + lane * 4);
    float4 w = *(const float4*)(a_src + t * 128 + lane * 4);
    float4 u = *(const float4*)(a_dst + t * 128 + lane * 4);
    float ps = v.x * w.x + v.y * w.y + v.z * w.z + v.w * w.w;
    float pd = v.x * u.x + v.y * u.y + v.z * u.z + v.w * u.w;
    ps += __shfl_xor_sync(0xffffffffu, ps, 1);
    ps += __shfl_xor_sync(0xffffffffu, ps, 2);
    pd += __shfl_xor_sync(0xffffffffu, pd, 1);
    pd += __shfl_xor_sync(0xffffffffu, pd, 2);
    if ((lane & 3) == 0) {
        ss[t * N_ * 8 + node * 8 + (lane >> 2)] = ps;
        sd[t * N_ * 8 + node * 8 + (lane >> 2)] = pd;
    }
}

// ---------------- layer-1 GAT: single pass (unnormalized + divide), fused scores2 ----------------
__global__ void __launch_bounds__(256) k_gat1(
    const int* __restrict__ offs, const int* __restrict__ cnt, const int* __restrict__ csr,
    const float* __restrict__ s1s, const float* __restrict__ s1d,
    const float* __restrict__ h1, const float* __restrict__ b1,
    float* __restrict__ h1c,
    const float* __restrict__ ws, const float* __restrict__ wd,
    float* __restrict__ s2s, float* __restrict__ s2d)
{
    __shared__ float sa[8][256];
    __shared__ float4 accs[8][32];
    int w = threadIdx.x >> 5, lane = threadIdx.x & 31;
    int d = blockIdx.x * 4 + (w >> 1);
    int t = w & 1;
    int hd = lane >> 2;
    float4 acc = make_float4(0.f, 0.f, 0.f, 0.f);
    if (d < N_) {
        int beg = offs[t * N_ + d], n = cnt[t * N_ + d];
        const float* ss = s1s + (size_t)t * N_ * 8;
        const float4* sdp = (const float4*)(s1d + ((size_t)t * N_ + d) * 8);
        float4 sd0 = sdp[0], sd1 = sdp[1];
        float sdv[8] = {sd0.x, sd0.y, sd0.z, sd0.w, sd1.x, sd1.y, sd1.z, sd1.w};
        const int* cs = csr + (size_t)t * E_ + beg;
        float zp = 0.f;
        for (int c0 = 0; c0 < n; c0 += 32) {
            int m = n - c0; if (m > 32) m = 32;
            int sL = 0;
            if (lane < m) {
                sL = cs[c0 + lane];
                float4 a0 = *(const float4*)(ss + (size_t)sL * 8);
                float4 a1 = *(const float4*)(ss + (size_t)sL * 8 + 4);
                float4 e0, e1;
                e0.x = __expf(lrelu(a0.x + sdv[0]));
                e0.y = __expf(lrelu(a0.y + sdv[1]));
                e0.z = __expf(lrelu(a0.z + sdv[2]));
                e0.w = __expf(lrelu(a0.w + sdv[3]));
                e1.x = __expf(lrelu(a1.x + sdv[4]));
                e1.y = __expf(lrelu(a1.y + sdv[5]));
                e1.z = __expf(lrelu(a1.z + sdv[6]));
                e1.w = __expf(lrelu(a1.w + sdv[7]));
                *(float4*)&sa[w][lane * 8] = e0;
                *(float4*)&sa[w][lane * 8 + 4] = e1;
            }
            __syncwarp();
#pragma unroll
            for (int j = 0; j < 32; j++) {
                if (j < m) {
                    int sj = __shfl_sync(0xffffffffu, sL, j);
                    float a = sa[w][j * 8 + hd];
                    zp += a;
                    float4 v = *(const float4*)(h1 + (size_t)sj * 256 + t * 128 + lane * 4);
                    acc.x = fmaf(a, v.x, acc.x);
                    acc.y = fmaf(a, v.y, acc.y);
                    acc.z = fmaf(a, v.z, acc.z);
                    acc.w = fmaf(a, v.w, acc.w);
                }
            }
            __syncwarp();
        }
        float inv = (zp > 0.f) ? 1.f / zp : 0.f;
        acc.x *= inv; acc.y *= inv; acc.z *= inv; acc.w *= inv;
    }
    accs[w][lane] = acc;
    __syncthreads();
    if (t == 0 && d < N_) {
        float4 a0 = accs[w][lane], a1 = accs[w + 1][lane];
        float4 bb0 = *(const float4*)(b1 + lane * 4);
        float4 bb1 = *(const float4*)(b1 + 128 + lane * 4);
        float4 r;
        r.x = eluf(0.5f * (a0.x + a1.x + bb0.x + bb1.x));
        r.y = eluf(0.5f * (a0.y + a1.y + bb0.y + bb1.y));
        r.z = eluf(0.5f * (a0.z + a1.z + bb0.z + bb1.z));
        r.w = eluf(0.5f * (a0.w + a1.w + bb0.w + bb1.w));
        *(float4*)(h1c + (size_t)d * 128 + lane * 4) = r;
#pragma unroll
        for (int c = 0; c < 16; c++) {
            float4 wv = *(const float4*)(ws + c * 128 + lane * 4);
            float p = r.x * wv.x + r.y * wv.y + r.z * wv.z + r.w * wv.w;
            p += __shfl_xor_sync(0xffffffffu, p, 16);
            p += __shfl_xor_sync(0xffffffffu, p, 8);
            p += __shfl_xor_sync(0xffffffffu, p, 4);
            p += __shfl_xor_sync(0xffffffffu, p, 2);
            p += __shfl_xor_sync(0xffffffffu, p, 1);
            float4 uv = *(const float4*)(wd + c * 128 + lane * 4);
            float q = r.x * uv.x + r.y * uv.y + r.z * uv.z + r.w * uv.w;
            q += __shfl_xor_sync(0xffffffffu, q, 16);
            q += __shfl_xor_sync(0xffffffffu, q, 8);
            q += __shfl_xor_sync(0xffffffffu, q, 4);
            q += __shfl_xor_sync(0xffffffffu, q, 2);
            q += __shfl_xor_sync(0xffffffffu, q, 1);
            if (lane == 0) {
                s2s[(c >> 3) * N_ * 8 + d * 8 + (c & 7)] = p;
                s2d[(c >> 3) * N_ * 8 + d * 8 + (c & 7)] = q;
            }
        }
    }
}

// ---------------- layer-2 aggregate: single pass -> bf16 hi|lo ----------------
__global__ void __launch_bounds__(256) k_gat2(
    const int* __restrict__ offs, const int* __restrict__ cnt, const int* __restrict__ csr,
    const float* __restrict__ s2s, const float* __restrict__ s2d,
    const float* __restrict__ h1c, uint16_t* __restrict__ aggb)
{
    __shared__ float sa[8][256];
    int w = threadIdx.x >> 5, lane = threadIdx.x & 31;
    int d = blockIdx.x * 4 + (w >> 1);
    int t = w & 1;
    if (d >= N_) return;
    int beg = offs[t * N_ + d], n = cnt[t * N_ + d];
    const float* ss = s2s + (size_t)t * N_ * 8;
    const float4* sdp = (const float4*)(s2d + ((size_t)t * N_ + d) * 8);
    float4 sd0 = sdp[0], sd1 = sdp[1];
    float sdv[8] = {sd0.x, sd0.y, sd0.z, sd0.w, sd1.x, sd1.y, sd1.z, sd1.w};
    const int* cs = csr + (size_t)t * E_ + beg;
    float z8[8];
#pragma unroll
    for (int k = 0; k < 8; k++) z8[k] = 0.f;
    float4 acc[8];
#pragma unroll
    for (int h = 0; h < 8; h++) acc[h] = make_float4(0.f, 0.f, 0.f, 0.f);
    for (int c0 = 0; c0 < n; c0 += 32) {
        int m = n - c0; if (m > 32) m = 32;
        int sL = 0;
        if (lane < m) {
            sL = cs[c0 + lane];
            float4 a0 = *(const float4*)(ss + (size_t)sL * 8);
            float4 a1 = *(const float4*)(ss + (size_t)sL * 8 + 4);
            float4 e0, e1;
            e0.x = __expf(lrelu(a0.x + sdv[0]));
            e0.y = __expf(lrelu(a0.y + sdv[1]));
            e0.z = __expf(lrelu(a0.z + sdv[2]));
            e0.w = __expf(lrelu(a0.w + sdv[3]));
            e1.x = __expf(lrelu(a1.x + sdv[4]));
            e1.y = __expf(lrelu(a1.y + sdv[5]));
            e1.z = __expf(lrelu(a1.z + sdv[6]));
            e1.w = __expf(lrelu(a1.w + sdv[7]));
            *(float4*)&sa[w][lane * 8] = e0;
            *(float4*)&sa[w][lane * 8 + 4] = e1;
        }
        __syncwarp();
#pragma unroll
        for (int j = 0; j < 32; j++) {
            if (j < m) {
                int sj = __shfl_sync(0xffffffffu, sL, j);
                float4 a0 = *(const float4*)&sa[w][j * 8];
                float4 a1 = *(const float4*)&sa[w][j * 8 + 4];
                z8[0] += a0.x; z8[1] += a0.y; z8[2] += a0.z; z8[3] += a0.w;
                z8[4] += a1.x; z8[5] += a1.y; z8[6] += a1.z; z8[7] += a1.w;
                float4 v = *(const float4*)(h1c + (size_t)sj * 128 + lane * 4);
                acc[0].x = fmaf(a0.x, v.x, acc[0].x); acc[0].y = fmaf(a0.x, v.y, acc[0].y);
                acc[0].z = fmaf(a0.x, v.z, acc[0].z); acc[0].w = fmaf(a0.x, v.w, acc[0].w);
                acc[1].x = fmaf(a0.y, v.x, acc[1].x); acc[1].y = fmaf(a0.y, v.y, acc[1].y);
                acc[1].z = fmaf(a0.y, v.z, acc[1].z); acc[1].w = fmaf(a0.y, v.w, acc[1].w);
                acc[2].x = fmaf(a0.z, v.x, acc[2].x); acc[2].y = fmaf(a0.z, v.y, acc[2].y);
                acc[2].z = fmaf(a0.z, v.z, acc[2].z); acc[2].w = fmaf(a0.z, v.w, acc[2].w);
                acc[3].x = fmaf(a0.w, v.x, acc[3].x); acc[3].y = fmaf(a0.w, v.y, acc[3].y);
                acc[3].z = fmaf(a0.w, v.z, acc[3].z); acc[3].w = fmaf(a0.w, v.w, acc[3].w);
                acc[4].x = fmaf(a1.x, v.x, acc[4].x); acc[4].y = fmaf(a1.x, v.y, acc[4].y);
                acc[4].z = fmaf(a1.x, v.z, acc[4].z); acc[4].w = fmaf(a1.x, v.w, acc[4].w);
                acc[5].x = fmaf(a1.y, v.x, acc[5].x); acc[5].y = fmaf(a1.y, v.y, acc[5].y);
                acc[5].z = fmaf(a1.y, v.z, acc[5].z); acc[5].w = fmaf(a1.y, v.w, acc[5].w);
                acc[6].x = fmaf(a1.z, v.x, acc[6].x); acc[6].y = fmaf(a1.z, v.y, acc[6].y);
                acc[6].z = fmaf(a1.z, v.z, acc[6].z); acc[6].w = fmaf(a1.z, v.w, acc[6].w);
                acc[7].x = fmaf(a1.w, v.x, acc[7].x); acc[7].y = fmaf(a1.w, v.y, acc[7].y);
                acc[7].z = fmaf(a1.w, v.z, acc[7].z); acc[7].w = fmaf(a1.w, v.w, acc[7].w);
            }
        }
        __syncwarp();
    }
#pragma unroll
    for (int h = 0; h < 8; h++) {
        float inv = (z8[h] > 0.f) ? 1.f / z8[h] : 0.f;
        float4 a = acc[h];
        a.x *= inv; a.y *= inv; a.z *= inv; a.w *= inv;
        uint16_t h0, l0, h1v, l1, h2, l2, h3, l3;
        hl_split(a.x, h0, l0); hl_split(a.y, h1v, l1);
        hl_split(a.z, h2, l2); hl_split(a.w, h3, l3);
        uint2 hi, lo;
        hi.x = (uint32_t)h0 | ((uint32_t)h1v << 16);
        hi.y = (uint32_t)h2 | ((uint32_t)h3 << 16);
        lo.x = (uint32_t)l0 | ((uint32_t)l1 << 16);
        lo.y = (uint32_t)l2 | ((uint32_t)l3 << 16);
        int k = t * 1024 + h * 128 + lane * 4;
        *(uint2*)(aggb + (size_t)d * 4096 + k) = hi;
        *(uint2*)(aggb + (size_t)d * 4096 + 2048 + k) = lo;
    }
}

// ---------------- classifier (sums 4 split-K parts, bias + ELU fused) ----------------
__global__ void k_classifier(const float* __restrict__ h, const float* __restrict__ bc,
                             const float* __restrict__ Wc1, const float* __restrict__ bc1,
                             const float* __restrict__ Wc2, const float* __restrict__ bc2,
                             float* __restrict__ out)
{
    int wid = (blockIdx.x * blockDim.x + threadIdx.x) >> 5;
    int lane = threadIdx.x & 31;
    if (wid >= N_) return;
    const float* hr0 = h + (size_t)wid * 64;
    const float* hr1 = hr0 + (size_t)N_ * 64;
    const float* hr2 = hr1 + (size_t)N_ * 64;
    const float* hr3 = hr2 + (size_t)N_ * 64;
    float acc = bc1[lane];
#pragma unroll
    for (int c = 0; c < 64; c++) {
        float hv = eluf(__ldg(hr0 + c) + __ldg(hr1 + c) + __ldg(hr2 + c) + __ldg(hr3 + c)
                        + __ldg(bc + c));
        acc = fmaf(hv, Wc1[c * 32 + lane], acc);
    }
    acc = fmaxf(acc, 0.f);
    float p0 = acc * Wc2[lane * 2];
    float p1 = acc * Wc2[lane * 2 + 1];
#pragma unroll
    for (int o = 16; o >= 1; o >>= 1) {
        p0 += __shfl_xor_sync(0xffffffffu, p0, o);
        p1 += __shfl_xor_sync(0xffffffffu, p1, o);
    }
    if (lane == 0) {
        out[wid * 2 + 0] = p0 + bc2[0];
        out[wid * 2 + 1] = p1 + bc2[1];
    }
}

// ---------------- launch ----------------
extern "C" void kernel_launch(void* const* d_in, const int* in_sizes, int n_in,
                              void* d_out, int out_size)
{
    const float* x    = (const float*)d_in[0];
    const void*  eia  = d_in[1];
    const void*  eib  = d_in[2];
    const float* W1   = (const float*)d_in[3];
    const float* a1s  = (const float*)d_in[4];
    const float* a1d  = (const float*)d_in[5];
    const float* b1   = (const float*)d_in[6];
    const float* W2   = (const float*)d_in[7];
    const float* a2s  = (const float*)d_in[8];
    const float* a2d  = (const float*)d_in[9];
    const float* b2   = (const float*)d_in[10];
    const float* Wc1  = (const float*)d_in[11];
    const float* bc1  = (const float*)d_in[12];
    const float* Wc2  = (const float*)d_in[13];
    const float* bc2  = (const float*)d_in[14];
    float* out = (float*)d_out;

    void* basev = nullptr;
    cudaGetSymbolAddress(&basev, g_scratch);
    unsigned char* base = (unsigned char*)basev;

    int*      p_csr  = (int*)(base + O_CSR);
    int*      p_cnt  = (int*)(base + O_CNT);
    int*      p_off  = (int*)(base + O_OFF);
    int*      p_cur  = (int*)(base + O_CUR);
    uint16_t* p_xb   = (uint16_t*)(base + O_XB);
    float*    p_h1   = (float*)(base + O_H1);
    float*    p_s1s  = (float*)(base + O_S1S);
    float*    p_s1d  = (float*)(base + O_S1D);
    float*    p_h1c  = (float*)(base + O_H1C);
    float*    p_s2s  = (float*)(base + O_S2S);
    float*    p_s2d  = (float*)(base + O_S2D);
    float*    p_ws   = (float*)(base + O_WS);
    float*    p_wd   = (float*)(base + O_WD);
    float*    p_bc   = (float*)(base + O_BC);
    uint16_t* p_wt1  = (uint16_t*)(base + O_WT1);
    uint16_t* p_wt2  = (uint16_t*)(base + O_WT2);
    uint16_t* p_aggb = (uint16_t*)(base + O_AGGB);
    int*      p_src  = (int*)(base + O_SRC);
    int*      p_dst  = (int*)(base + O_DST);
    float*    p_h2p  = (float*)(base + O_H2P);

    cudaFuncSetAttribute(k_mmagemm<4, 512, 512>,
                         cudaFuncAttributeMaxDynamicSharedMemorySize, 73728);
    cudaFuncSetAttribute(k_mmagemm<32, 4096, 4096>,
                         cudaFuncAttributeMaxDynamicSharedMemorySize, 73728);

    // 1-3: prep (zeros cnt), cvt (+histogram), cvtx
    k_prep<<<(240768 + 255) / 256, 256>>>(W2, a2s, a2d, b2, W1, p_wt1, p_wt2,
                                          p_ws, p_wd, p_bc, p_cnt);
    k_cvt<<<dim3((E_ + 255) / 256, 2), 256>>>(eia, eib, p_src, p_dst, p_cnt);
    k_cvtx<<<(N_ * 64 + 255) / 256, 256>>>(x, p_xb);

    // 4: layer-1 GEMM (ncu profiles this launch)
    k_mmagemm<4, 512, 512><<<dim3(157, 4, 1), 256, 73728>>>(p_xb, p_wt1, p_h1, N_, 256, 0);

    // 5-6: finish CSR
    k_scan<<<2, 1024>>>(p_cnt, p_off, p_cur);
    k_scatter<<<(2 * E_ + 255) / 256, 256>>>(p_src, p_dst, p_cur, p_csr);

    // 7-9: scores -> gat1 (h1c + layer-2 scores) -> gat2
    k_scores1<<<dim3((N_ + 7) / 8, 2), 256>>>(p_h1, a1s, a1d, p_s1s, p_s1d);
    k_gat1<<<(N_ + 3) / 4, 256>>>(p_off, p_cnt, p_csr, p_s1s, p_s1d, p_h1, b1,
                                  p_h1c, p_ws, p_wd, p_s2s, p_s2d);
    k_gat2<<<(N_ + 3) / 4, 256>>>(p_off, p_cnt, p_csr, p_s2s, p_s2d, p_h1c, p_aggb);

    // 10: layer-2 GEMM, split-K=4
    k_mmagemm<32, 4096, 4096><<<dim3(157, 1, 4), 256, 73728>>>(
        p_aggb, p_wt2, p_h2p, N_, 64, (size_t)N_ * 64);

    // 11: classifier
    k_classifier<<<(N_ * 32 + 255) / 256, 256>>>(p_h2p, p_bc, Wc1, bc1, Wc2, bc2, out);
}